// round 1
// baseline (speedup 1.0000x reference)
#include <cuda_runtime.h>
#include <cuda_bf16.h>
#include <math.h>

// Problem shape (fixed by reference): B=4, S=2048, D=1024
#define BATCH 4
#define SEQ   2048
#define DIM   1024
#define NTOK  (BATCH * SEQ)   // 8192

// ---------------------------------------------------------------------------
// Scratch (static device globals; no runtime allocation allowed)
// ---------------------------------------------------------------------------
__device__ float g_Q[NTOK * DIM];                 // 32 MB
__device__ float g_K[NTOK * DIM];                 // 32 MB
__device__ float g_V[NTOK * DIM];                 // 32 MB
__device__ float g_P[BATCH * SEQ * SEQ];          // 64 MB (scores -> probs)

// ---------------------------------------------------------------------------
// SGEMM-NN: C[M,N] = A[M,K] * B[K,N], all row-major, fp32.
// BM=BN=128, BK=8, 256 threads, 8x8 register tile per thread.
// Optional k-clamp: loop runs k < min(K, blockRow+BM) when CLAMPK != 0
// (used for the PV GEMM where P is causally zero beyond the row block).
// ---------------------------------------------------------------------------
template <int CLAMPK>
__global__ __launch_bounds__(256)
void sgemm_nn(const float* __restrict__ A, const float* __restrict__ Bm,
              float* __restrict__ C, int M, int N, int K,
              long strideA, long strideB, long strideC)
{
    const int BM = 128, BN = 128, BK = 8, TM = 8, TN = 8;
    __shared__ float As[BK][BM];
    __shared__ float Bs[BK][BN];

    A  += (long)blockIdx.z * strideA;
    Bm += (long)blockIdx.z * strideB;
    C  += (long)blockIdx.z * strideC;

    const int tid = threadIdx.x;
    const int brow0 = blockIdx.y * BM;
    const int bcol0 = blockIdx.x * BN;

    // A-tile loader: 128x8 floats, thread t -> row t/2, 4 cols at (t%2)*4
    const int arow = tid >> 1, acol = (tid & 1) * 4;
    // B-tile loader: 8x128 floats, thread t -> row t/32, 4 cols at (t%32)*4
    const int bro  = tid >> 5, bco = (tid & 31) * 4;

    const int ty = tid >> 4, tx = tid & 15;   // 16x16 thread grid

    float acc[TM][TN];
#pragma unroll
    for (int i = 0; i < TM; i++)
#pragma unroll
        for (int j = 0; j < TN; j++) acc[i][j] = 0.f;

    const int kend = CLAMPK ? min(K, brow0 + BM) : K;

    for (int k0 = 0; k0 < kend; k0 += BK) {
        float4 a4 = *(const float4*)(A + (long)(brow0 + arow) * K + k0 + acol);
        As[acol + 0][arow] = a4.x;
        As[acol + 1][arow] = a4.y;
        As[acol + 2][arow] = a4.z;
        As[acol + 3][arow] = a4.w;
        float4 b4 = *(const float4*)(Bm + (long)(k0 + bro) * N + bcol0 + bco);
        *(float4*)&Bs[bro][bco] = b4;
        __syncthreads();

#pragma unroll
        for (int kk = 0; kk < BK; ++kk) {
            float ar[TM], br[TN];
            float4 t0 = *(const float4*)&As[kk][ty * TM];
            float4 t1 = *(const float4*)&As[kk][ty * TM + 4];
            ar[0]=t0.x; ar[1]=t0.y; ar[2]=t0.z; ar[3]=t0.w;
            ar[4]=t1.x; ar[5]=t1.y; ar[6]=t1.z; ar[7]=t1.w;
            float4 u0 = *(const float4*)&Bs[kk][tx * TN];
            float4 u1 = *(const float4*)&Bs[kk][tx * TN + 4];
            br[0]=u0.x; br[1]=u0.y; br[2]=u0.z; br[3]=u0.w;
            br[4]=u1.x; br[5]=u1.y; br[6]=u1.z; br[7]=u1.w;
#pragma unroll
            for (int i = 0; i < TM; i++)
#pragma unroll
                for (int j = 0; j < TN; j++)
                    acc[i][j] += ar[i] * br[j];
        }
        __syncthreads();
    }

#pragma unroll
    for (int i = 0; i < TM; i++) {
        float* crow = C + (long)(brow0 + ty * TM + i) * N + bcol0 + tx * TN;
        *(float4*)(crow + 0) = make_float4(acc[i][0], acc[i][1], acc[i][2], acc[i][3]);
        *(float4*)(crow + 4) = make_float4(acc[i][4], acc[i][5], acc[i][6], acc[i][7]);
    }
}

// ---------------------------------------------------------------------------
// SGEMM-NT: C[M,N] = A[M,K] * B[N,K]^T  (scores = Q @ K^T per batch).
// Skips blocks entirely above the causal diagonal.
// ---------------------------------------------------------------------------
__global__ __launch_bounds__(256)
void sgemm_nt_causal(const float* __restrict__ A, const float* __restrict__ Bt,
                     float* __restrict__ C, int M, int N, int K,
                     long strideA, long strideB, long strideC)
{
    const int BM = 128, BN = 128, BK = 8, TM = 8, TN = 8;

    const int brow0 = blockIdx.y * BM;
    const int bcol0 = blockIdx.x * BN;
    if (bcol0 >= brow0 + BM) return;   // fully above the diagonal -> masked out

    __shared__ float As[BK][BM];
    __shared__ float Bs[BK][BN];

    A  += (long)blockIdx.z * strideA;
    Bt += (long)blockIdx.z * strideB;
    C  += (long)blockIdx.z * strideC;

    const int tid = threadIdx.x;
    const int arow = tid >> 1, acol = (tid & 1) * 4;
    const int ty = tid >> 4, tx = tid & 15;

    float acc[TM][TN];
#pragma unroll
    for (int i = 0; i < TM; i++)
#pragma unroll
        for (int j = 0; j < TN; j++) acc[i][j] = 0.f;

    for (int k0 = 0; k0 < K; k0 += BK) {
        float4 a4 = *(const float4*)(A + (long)(brow0 + arow) * K + k0 + acol);
        As[acol + 0][arow] = a4.x;
        As[acol + 1][arow] = a4.y;
        As[acol + 2][arow] = a4.z;
        As[acol + 3][arow] = a4.w;
        // B^T tile: rows of Bt are the N dimension; same access shape as A
        float4 b4 = *(const float4*)(Bt + (long)(bcol0 + arow) * K + k0 + acol);
        Bs[acol + 0][arow] = b4.x;
        Bs[acol + 1][arow] = b4.y;
        Bs[acol + 2][arow] = b4.z;
        Bs[acol + 3][arow] = b4.w;
        __syncthreads();

#pragma unroll
        for (int kk = 0; kk < BK; ++kk) {
            float ar[TM], br[TN];
            float4 t0 = *(const float4*)&As[kk][ty * TM];
            float4 t1 = *(const float4*)&As[kk][ty * TM + 4];
            ar[0]=t0.x; ar[1]=t0.y; ar[2]=t0.z; ar[3]=t0.w;
            ar[4]=t1.x; ar[5]=t1.y; ar[6]=t1.z; ar[7]=t1.w;
            float4 u0 = *(const float4*)&Bs[kk][tx * TN];
            float4 u1 = *(const float4*)&Bs[kk][tx * TN + 4];
            br[0]=u0.x; br[1]=u0.y; br[2]=u0.z; br[3]=u0.w;
            br[4]=u1.x; br[5]=u1.y; br[6]=u1.z; br[7]=u1.w;
#pragma unroll
            for (int i = 0; i < TM; i++)
#pragma unroll
                for (int j = 0; j < TN; j++)
                    acc[i][j] += ar[i] * br[j];
        }
        __syncthreads();
    }

#pragma unroll
    for (int i = 0; i < TM; i++) {
        float* crow = C + (long)(brow0 + ty * TM + i) * N + bcol0 + tx * TN;
        *(float4*)(crow + 0) = make_float4(acc[i][0], acc[i][1], acc[i][2], acc[i][3]);
        *(float4*)(crow + 4) = make_float4(acc[i][4], acc[i][5], acc[i][6], acc[i][7]);
    }
}

// ---------------------------------------------------------------------------
// Causal row softmax over P (in place). One 256-thread block per row.
// Reads j in [0, q], writes normalized probs there and zeros j in (q, S).
// Applies the 1/sqrt(D) = 1/32 score scale.
// ---------------------------------------------------------------------------
__global__ __launch_bounds__(256)
void softmax_causal(float* __restrict__ P)
{
    const int q = blockIdx.x;
    const int b = blockIdx.y;
    float* row = P + ((long)b * SEQ + q) * SEQ;
    const int n = q + 1;
    const float scale = 0.03125f;  // 1/sqrt(1024)

    const int tid = threadIdx.x;
    float vals[8];                 // ceil(2048/256) = 8 max
    int cnt = 0;
    float m = -1e30f;
    for (int j = tid; j < n; j += 256) {
        float v = row[j] * scale;
        vals[cnt++] = v;
        m = fmaxf(m, v);
    }

    __shared__ float red[256];
    red[tid] = m;
    __syncthreads();
#pragma unroll
    for (int s = 128; s > 0; s >>= 1) {
        if (tid < s) red[tid] = fmaxf(red[tid], red[tid + s]);
        __syncthreads();
    }
    m = red[0];
    __syncthreads();

    float sum = 0.f;
    for (int i = 0; i < cnt; i++) {
        vals[i] = __expf(vals[i] - m);
        sum += vals[i];
    }
    red[tid] = sum;
    __syncthreads();
#pragma unroll
    for (int s = 128; s > 0; s >>= 1) {
        if (tid < s) red[tid] += red[tid + s];
        __syncthreads();
    }
    const float inv = 1.0f / red[0];

    cnt = 0;
    for (int j = tid; j < n; j += 256) row[j] = vals[cnt++] * inv;
    for (int j = n + tid; j < SEQ; j += 256) row[j] = 0.f;  // zero above diagonal
}

// ---------------------------------------------------------------------------
// Host launcher
// ---------------------------------------------------------------------------
extern "C" void kernel_launch(void* const* d_in, const int* in_sizes, int n_in,
                              void* d_out, int out_size)
{
    (void)in_sizes; (void)n_in; (void)out_size;
    const float* x  = (const float*)d_in[0];
    const float* Qw = (const float*)d_in[1];
    const float* Kw = (const float*)d_in[2];
    const float* Vw = (const float*)d_in[3];
    float* out = (float*)d_out;

    float *Qp, *Kp, *Vp, *Pp;
    cudaGetSymbolAddress((void**)&Qp, g_Q);
    cudaGetSymbolAddress((void**)&Kp, g_K);
    cudaGetSymbolAddress((void**)&Vp, g_V);
    cudaGetSymbolAddress((void**)&Pp, g_P);

    // Stage 1: Q/K/V projections — [8192,1024] @ [1024,1024]
    {
        dim3 grid(DIM / 128, NTOK / 128, 1);
        sgemm_nn<0><<<grid, 256>>>(x, Qw, Qp, NTOK, DIM, DIM, 0, 0, 0);
        sgemm_nn<0><<<grid, 256>>>(x, Kw, Kp, NTOK, DIM, DIM, 0, 0, 0);
        sgemm_nn<0><<<grid, 256>>>(x, Vw, Vp, NTOK, DIM, DIM, 0, 0, 0);
    }

    // Stage 2: scores = Q @ K^T per batch (lower-triangular blocks only)
    {
        dim3 grid(SEQ / 128, SEQ / 128, BATCH);
        sgemm_nt_causal<<<grid, 256>>>(Qp, Kp, Pp, SEQ, SEQ, DIM,
                                       (long)SEQ * DIM, (long)SEQ * DIM,
                                       (long)SEQ * SEQ);
    }

    // Stage 3: causal softmax in place (also zero-fills above diagonal)
    {
        dim3 grid(SEQ, BATCH, 1);
        softmax_causal<<<grid, 256>>>(Pp);
    }

    // Stage 4: out = P @ V per batch, k clamped to causal row-block extent
    {
        dim3 grid(DIM / 128, SEQ / 128, BATCH);
        sgemm_nn<1><<<grid, 256>>>(Pp, Vp, out, SEQ, DIM, SEQ,
                                   (long)SEQ * SEQ, (long)SEQ * DIM,
                                   (long)SEQ * DIM);
    }
}

// round 3
// speedup vs baseline: 2.5312x; 2.5312x over previous
#include <cuda_runtime.h>
#include <cuda_fp16.h>
#include <math.h>
#include <stdint.h>

// Problem shape (fixed by reference): B=4, S=2048, D=1024
#define BATCH 4
#define SEQ   2048
#define DIM   1024
#define NTOK  (BATCH * SEQ)   // 8192

// ---------------------------------------------------------------------------
// Scratch (static device globals; no runtime allocation allowed)
// ---------------------------------------------------------------------------
__device__ float g_V[NTOK * DIM];                 // fp32 V (pre-transpose)
__device__ float g_P[BATCH * SEQ * SEQ];          // fp32 scores

__device__ __half g_xh[NTOK * DIM],  g_xl[NTOK * DIM];
__device__ __half g_Qwh[DIM * DIM],  g_Qwl[DIM * DIM];   // W^T [N,K]
__device__ __half g_Kwh[DIM * DIM],  g_Kwl[DIM * DIM];
__device__ __half g_Vwh[DIM * DIM],  g_Vwl[DIM * DIM];
__device__ __half g_Qh[NTOK * DIM],  g_Ql[NTOK * DIM];
__device__ __half g_Kh[NTOK * DIM],  g_Kl[NTOK * DIM];
__device__ __half g_Vth[NTOK * DIM], g_Vtl[NTOK * DIM];  // per-batch [D,S]
__device__ __half g_Ph[BATCH * SEQ * SEQ], g_Pl[BATCH * SEQ * SEQ];

// ---------------------------------------------------------------------------
// Helpers
// ---------------------------------------------------------------------------
__device__ __forceinline__ uint32_t smem_u32(const void* p) {
    uint32_t a;
    asm("{ .reg .u64 t; cvta.to.shared.u64 t, %1; cvt.u32.u64 %0, t; }" : "=r"(a) : "l"(p));
    return a;
}

#define CP16(dst, src) \
    asm volatile("cp.async.cg.shared.global [%0], [%1], 16;" :: "r"(dst), "l"(src))

#define LDSM4(r, addr) \
    asm volatile("ldmatrix.sync.aligned.m8n8.x4.shared.b16 {%0,%1,%2,%3}, [%4];" \
        : "=r"((r)[0]), "=r"((r)[1]), "=r"((r)[2]), "=r"((r)[3]) : "r"(addr))

#define MMA4(c, a, b0, b1) \
    asm volatile("mma.sync.aligned.m16n8k16.row.col.f32.f16.f16.f32 " \
        "{%0,%1,%2,%3}, {%4,%5,%6,%7}, {%8,%9}, {%0,%1,%2,%3};" \
        : "+f"((c)[0]), "+f"((c)[1]), "+f"((c)[2]), "+f"((c)[3]) \
        : "r"((a)[0]), "r"((a)[1]), "r"((a)[2]), "r"((a)[3]), "r"(b0), "r"(b1))

// ---------------------------------------------------------------------------
// HMMA GEMM: C[M,N] = A[M,K] @ B[N,K]^T with fp16 2-way split, 3 products,
// fp32 accumulate. CTA tile 128x128, BK=32, 8 warps (2x4), warp tile 64x32.
// Smem: per stage 4 tiles (Ah, Al, Bh, Bl) of 128 rows x 64B data @ 80B pitch
//       (80B pitch => conflict-free ldmatrix). 2 stages, cp.async pipelined.
// MODE: 0 plain, 1 causal block-skip, 2 K clamped to brow0+128.
// EPI:  0 -> fp32 C;  1 -> write hi/lo fp16 split (Ch, Cl).
// ---------------------------------------------------------------------------
#define TILE_B   10240           // 128 * 80
#define STAGE_B  (4 * TILE_B)    // 40960
#define GEMM_SMEM (2 * STAGE_B)  // 81920

template <int MODE, int EPI>
__global__ void __launch_bounds__(256, 1)
gemm_hmma(const __half* __restrict__ Ah, const __half* __restrict__ Al,
          const __half* __restrict__ Bh, const __half* __restrict__ Bl,
          float* __restrict__ C, __half* __restrict__ Ch, __half* __restrict__ Cl,
          int K, int ldc, long sA, long sB, long sC)
{
    const int brow0 = blockIdx.y * 128;
    const int bcol0 = blockIdx.x * 128;
    if (MODE == 1 && bcol0 > brow0) return;

    extern __shared__ char sm[];
    const uint32_t smb = smem_u32(sm);

    const int tid = threadIdx.x;
    const int lane = tid & 31;
    const int wid = tid >> 5;
    const int wr = wid >> 2;      // warp row (0..1): rows wr*64
    const int wc = wid & 3;       // warp col (0..3): cols wc*32

    Ah += (long)blockIdx.z * sA;  Al += (long)blockIdx.z * sA;
    Bh += (long)blockIdx.z * sB;  Bl += (long)blockIdx.z * sB;

    const int kend = (MODE == 2) ? (brow0 + 128) : K;
    const int nsteps = kend >> 5;

    // --- loader: one 32-wide K slab into stage s ---
    const int lrow = tid >> 2;          // 0..63
    const int lcol = tid & 3;           // 0..3 (16B chunks)
    const uint32_t so1 = (uint32_t)(lrow * 80 + lcol * 16);
    const uint32_t so2 = (uint32_t)((lrow + 64) * 80 + lcol * 16);

    auto load_stage = [&](int s, int k0) {
        uint32_t st = smb + s * STAGE_B;
        long gk = k0 + lcol * 8;
        CP16(st + 0 * TILE_B + so1, Ah + (long)(brow0 + lrow)      * K + gk);
        CP16(st + 0 * TILE_B + so2, Ah + (long)(brow0 + lrow + 64) * K + gk);
        CP16(st + 1 * TILE_B + so1, Al + (long)(brow0 + lrow)      * K + gk);
        CP16(st + 1 * TILE_B + so2, Al + (long)(brow0 + lrow + 64) * K + gk);
        CP16(st + 2 * TILE_B + so1, Bh + (long)(bcol0 + lrow)      * K + gk);
        CP16(st + 2 * TILE_B + so2, Bh + (long)(bcol0 + lrow + 64) * K + gk);
        CP16(st + 3 * TILE_B + so1, Bl + (long)(bcol0 + lrow)      * K + gk);
        CP16(st + 3 * TILE_B + so2, Bl + (long)(bcol0 + lrow + 64) * K + gk);
        asm volatile("cp.async.commit_group;");
    };

    float acc[4][4][4];
#pragma unroll
    for (int mt = 0; mt < 4; mt++)
#pragma unroll
        for (int nt = 0; nt < 4; nt++)
#pragma unroll
            for (int v = 0; v < 4; v++) acc[mt][nt][v] = 0.f;

    // ldmatrix per-thread intra-tile offsets
    const int arow = lane & 15;                       // A row within 16
    const int asel = lane >> 4;                       // A k-half (0/1)
    const int brow = (lane & 7) + ((lane >> 4) << 3); // B n row within 16
    const int bsel = (lane >> 3) & 1;                 // B k-half (0/1)

    load_stage(0, 0);

    for (int s = 0; s < nsteps; s++) {
        if (s + 1 < nsteps) {
            load_stage((s + 1) & 1, (s + 1) * 32);
            asm volatile("cp.async.wait_group 1;");
        } else {
            asm volatile("cp.async.wait_group 0;");
        }
        __syncthreads();

        const uint32_t st = smb + (s & 1) * STAGE_B;
#pragma unroll
        for (int kk = 0; kk < 2; kk++) {
            uint32_t aH[4][4], aL[4][4];
#pragma unroll
            for (int mt = 0; mt < 4; mt++) {
                uint32_t off = (uint32_t)((wr * 64 + mt * 16 + arow) * 80 + kk * 32 + asel * 16);
                LDSM4(aH[mt], st + 0 * TILE_B + off);
                LDSM4(aL[mt], st + 1 * TILE_B + off);
            }
            uint32_t bH[2][4], bL[2][4];
#pragma unroll
            for (int np = 0; np < 2; np++) {
                uint32_t off = (uint32_t)((wc * 32 + np * 16 + brow) * 80 + kk * 32 + bsel * 16);
                LDSM4(bH[np], st + 2 * TILE_B + off);
                LDSM4(bL[np], st + 3 * TILE_B + off);
            }
#pragma unroll
            for (int mt = 0; mt < 4; mt++)
#pragma unroll
                for (int nt = 0; nt < 4; nt++) {
                    const int np = nt >> 1, hv = (nt & 1) * 2;
                    MMA4(acc[mt][nt], aH[mt], bH[np][hv], bH[np][hv + 1]);
                    MMA4(acc[mt][nt], aH[mt], bL[np][hv], bL[np][hv + 1]);
                    MMA4(acc[mt][nt], aL[mt], bH[np][hv], bH[np][hv + 1]);
                }
        }
        __syncthreads();
    }

    // --- epilogue ---
    const int erow = lane >> 2;         // 0..7
    const int ecol = (lane & 3) * 2;
#pragma unroll
    for (int mt = 0; mt < 4; mt++) {
        const int row = brow0 + wr * 64 + mt * 16 + erow;
#pragma unroll
        for (int nt = 0; nt < 4; nt++) {
            const int col = bcol0 + wc * 32 + nt * 8 + ecol;
            const float* c = acc[mt][nt];
            if (EPI == 0) {
                float* Cb = C + (long)blockIdx.z * sC;
                *(float2*)(Cb + (long)row * ldc + col)       = make_float2(c[0], c[1]);
                *(float2*)(Cb + (long)(row + 8) * ldc + col) = make_float2(c[2], c[3]);
            } else {
                __half* Hb = Ch + (long)blockIdx.z * sC;
                __half* Lb = Cl + (long)blockIdx.z * sC;
                __half h0 = __float2half_rn(c[0]), h1 = __float2half_rn(c[1]);
                __half h2 = __float2half_rn(c[2]), h3 = __float2half_rn(c[3]);
                __half l0 = __float2half_rn(c[0] - __half2float(h0));
                __half l1 = __float2half_rn(c[1] - __half2float(h1));
                __half l2 = __float2half_rn(c[2] - __half2float(h2));
                __half l3 = __float2half_rn(c[3] - __half2float(h3));
                *(__half2*)(Hb + (long)row * ldc + col)       = __halves2half2(h0, h1);
                *(__half2*)(Hb + (long)(row + 8) * ldc + col) = __halves2half2(h2, h3);
                *(__half2*)(Lb + (long)row * ldc + col)       = __halves2half2(l0, l1);
                *(__half2*)(Lb + (long)(row + 8) * ldc + col) = __halves2half2(l2, l3);
            }
        }
    }
}

// ---------------------------------------------------------------------------
// Elementwise fp32 -> (hi, lo) fp16 split.
// ---------------------------------------------------------------------------
__global__ void __launch_bounds__(256)
split_fp32(const float* __restrict__ in, __half* __restrict__ hi,
           __half* __restrict__ lo, long n4)
{
    long i = (long)blockIdx.x * blockDim.x + threadIdx.x;
    long stride = (long)gridDim.x * blockDim.x;
    for (; i < n4; i += stride) {
        float4 v = ((const float4*)in)[i];
        float f[4] = {v.x, v.y, v.z, v.w};
        __half h[4], l[4];
#pragma unroll
        for (int j = 0; j < 4; j++) {
            h[j] = __float2half_rn(f[j]);
            l[j] = __float2half_rn(f[j] - __half2float(h[j]));
        }
        ((uint2*)hi)[i] = *(uint2*)h;
        ((uint2*)lo)[i] = *(uint2*)l;
    }
}

// ---------------------------------------------------------------------------
// Transpose + split: fp32 [R, C] -> fp16 hi/lo [C, R], batched.
// ---------------------------------------------------------------------------
__global__ void __launch_bounds__(256)
transpose_split(const float* __restrict__ in, __half* __restrict__ oh,
                __half* __restrict__ ol, int R, int Cc, long sIn, long sOut)
{
    __shared__ float tile[32][33];
    const int b = blockIdx.z;
    const float* src = in + (long)b * sIn;
    const int c0 = blockIdx.x * 32, r0 = blockIdx.y * 32;
#pragma unroll
    for (int dy = threadIdx.y; dy < 32; dy += 8)
        tile[dy][threadIdx.x] = src[(long)(r0 + dy) * Cc + c0 + threadIdx.x];
    __syncthreads();
#pragma unroll
    for (int dy = threadIdx.y; dy < 32; dy += 8) {
        float v = tile[threadIdx.x][dy];
        long o = (long)b * sOut + (long)(c0 + dy) * R + r0 + threadIdx.x;
        __half h = __float2half_rn(v);
        oh[o] = h;
        ol[o] = __float2half_rn(v - __half2float(h));
    }
}

// ---------------------------------------------------------------------------
// Causal row softmax: reads fp32 scores, writes fp16 hi/lo probs (zero-filled
// above the diagonal). Applies 1/sqrt(D) scale.
// ---------------------------------------------------------------------------
__global__ void __launch_bounds__(256)
softmax_causal_split(const float* __restrict__ P, __half* __restrict__ Ph,
                     __half* __restrict__ Pl)
{
    const int q = blockIdx.x;
    const int b = blockIdx.y;
    const long rowoff = ((long)b * SEQ + q) * SEQ;
    const float* row = P + rowoff;
    __half* ph = Ph + rowoff;
    __half* pl = Pl + rowoff;
    const int n = q + 1;
    const float scale = 0.03125f;  // 1/sqrt(1024)

    const int tid = threadIdx.x;
    float vals[8];
    int cnt = 0;
    float m = -1e30f;
    for (int j = tid; j < n; j += 256) {
        float v = row[j] * scale;
        vals[cnt++] = v;
        m = fmaxf(m, v);
    }
    __shared__ float red[256];
    red[tid] = m;
    __syncthreads();
#pragma unroll
    for (int s = 128; s > 0; s >>= 1) {
        if (tid < s) red[tid] = fmaxf(red[tid], red[tid + s]);
        __syncthreads();
    }
    m = red[0];
    __syncthreads();
    float sum = 0.f;
    for (int i = 0; i < cnt; i++) { vals[i] = __expf(vals[i] - m); sum += vals[i]; }
    red[tid] = sum;
    __syncthreads();
#pragma unroll
    for (int s = 128; s > 0; s >>= 1) {
        if (tid < s) red[tid] += red[tid + s];
        __syncthreads();
    }
    const float inv = 1.0f / red[0];
    cnt = 0;
    for (int j = tid; j < n; j += 256) {
        float p = vals[cnt++] * inv;
        __half h = __float2half_rn(p);
        ph[j] = h;
        pl[j] = __float2half_rn(p - __half2float(h));
    }
    const __half z = __float2half_rn(0.f);
    for (int j = n + tid; j < SEQ; j += 256) { ph[j] = z; pl[j] = z; }
}

// ---------------------------------------------------------------------------
// Host launcher
// ---------------------------------------------------------------------------
extern "C" void kernel_launch(void* const* d_in, const int* in_sizes, int n_in,
                              void* d_out, int out_size)
{
    (void)in_sizes; (void)n_in; (void)out_size;
    const float* x  = (const float*)d_in[0];
    const float* Qw = (const float*)d_in[1];
    const float* Kw = (const float*)d_in[2];
    const float* Vw = (const float*)d_in[3];
    float* out = (float*)d_out;

    float *Vp, *Pp;
    cudaGetSymbolAddress((void**)&Vp, g_V);
    cudaGetSymbolAddress((void**)&Pp, g_P);
    __half *xh, *xl, *Qwh, *Qwl, *Kwh, *Kwl, *Vwh, *Vwl;
    __half *Qh, *Ql, *Kh, *Kl, *Vth, *Vtl, *Ph, *Pl;
    cudaGetSymbolAddress((void**)&xh,  g_xh);  cudaGetSymbolAddress((void**)&xl,  g_xl);
    cudaGetSymbolAddress((void**)&Qwh, g_Qwh); cudaGetSymbolAddress((void**)&Qwl, g_Qwl);
    cudaGetSymbolAddress((void**)&Kwh, g_Kwh); cudaGetSymbolAddress((void**)&Kwl, g_Kwl);
    cudaGetSymbolAddress((void**)&Vwh, g_Vwh); cudaGetSymbolAddress((void**)&Vwl, g_Vwl);
    cudaGetSymbolAddress((void**)&Qh,  g_Qh);  cudaGetSymbolAddress((void**)&Ql,  g_Ql);
    cudaGetSymbolAddress((void**)&Kh,  g_Kh);  cudaGetSymbolAddress((void**)&Kl,  g_Kl);
    cudaGetSymbolAddress((void**)&Vth, g_Vth); cudaGetSymbolAddress((void**)&Vtl, g_Vtl);
    cudaGetSymbolAddress((void**)&Ph,  g_Ph);  cudaGetSymbolAddress((void**)&Pl,  g_Pl);

    cudaFuncSetAttribute(gemm_hmma<0,0>, cudaFuncAttributeMaxDynamicSharedMemorySize, GEMM_SMEM);
    cudaFuncSetAttribute(gemm_hmma<0,1>, cudaFuncAttributeMaxDynamicSharedMemorySize, GEMM_SMEM);
    cudaFuncSetAttribute(gemm_hmma<1,0>, cudaFuncAttributeMaxDynamicSharedMemorySize, GEMM_SMEM);
    cudaFuncSetAttribute(gemm_hmma<2,0>, cudaFuncAttributeMaxDynamicSharedMemorySize, GEMM_SMEM);

    // --- Split / transpose inputs ---
    {
        split_fp32<<<1024, 256>>>(x, xh, xl, (long)NTOK * DIM / 4);
        dim3 tg(DIM / 32, DIM / 32, 1);
        dim3 tb(32, 8);
        transpose_split<<<tg, tb>>>(Qw, Qwh, Qwl, DIM, DIM, 0, 0);
        transpose_split<<<tg, tb>>>(Kw, Kwh, Kwl, DIM, DIM, 0, 0);
        transpose_split<<<tg, tb>>>(Vw, Vwh, Vwl, DIM, DIM, 0, 0);
    }

    // --- Projections: Q,K write fp16 splits directly; V writes fp32 ---
    {
        dim3 grid(DIM / 128, NTOK / 128, 1);
        gemm_hmma<0,1><<<grid, 256, GEMM_SMEM>>>(xh, xl, Qwh, Qwl, nullptr, Qh, Ql, DIM, DIM, 0, 0, 0);
        gemm_hmma<0,1><<<grid, 256, GEMM_SMEM>>>(xh, xl, Kwh, Kwl, nullptr, Kh, Kl, DIM, DIM, 0, 0, 0);
        gemm_hmma<0,0><<<grid, 256, GEMM_SMEM>>>(xh, xl, Vwh, Vwl, Vp, nullptr, nullptr, DIM, DIM, 0, 0, 0);
    }

    // --- Transpose+split V: [S,D] -> [D,S] per batch ---
    {
        dim3 tg(DIM / 32, SEQ / 32, BATCH);
        dim3 tb(32, 8);
        transpose_split<<<tg, tb>>>(Vp, Vth, Vtl, SEQ, DIM, (long)SEQ * DIM, (long)SEQ * DIM);
    }

    // --- Scores = Q @ K^T per batch (causal block-skip), fp32 out ---
    {
        dim3 grid(SEQ / 128, SEQ / 128, BATCH);
        gemm_hmma<1,0><<<grid, 256, GEMM_SMEM>>>(Qh, Ql, Kh, Kl, Pp, nullptr, nullptr,
                                                 DIM, SEQ,
                                                 (long)SEQ * DIM, (long)SEQ * DIM,
                                                 (long)SEQ * SEQ);
    }

    // --- Softmax: fp32 scores -> fp16 hi/lo probs ---
    softmax_causal_split<<<dim3(SEQ, BATCH, 1), 256>>>(Pp, Ph, Pl);

    // --- Out = P @ Vt^T per batch, K clamped causally ---
    {
        dim3 grid(DIM / 128, SEQ / 128, BATCH);
        gemm_hmma<2,0><<<grid, 256, GEMM_SMEM>>>(Ph, Pl, Vth, Vtl, out, nullptr, nullptr,
                                                 SEQ, DIM,
                                                 (long)SEQ * SEQ, (long)SEQ * DIM,
                                                 (long)SEQ * DIM);
    }
}

// round 4
// speedup vs baseline: 3.0010x; 1.1856x over previous
#include <cuda_runtime.h>
#include <cuda_fp16.h>
#include <math.h>
#include <stdint.h>

// Problem shape (fixed by reference): B=4, S=2048, D=1024
#define BATCH 4
#define SEQ   2048
#define DIM   1024
#define NTOK  (BATCH * SEQ)   // 8192

// ---------------------------------------------------------------------------
// Scratch (static device globals)
// ---------------------------------------------------------------------------
__device__ float g_P[BATCH * SEQ * SEQ];                     // fp32 scores

__device__ __half g_xh[NTOK * DIM],   g_xl[NTOK * DIM];
__device__ __half g_Wqkh[2048 * DIM], g_Wqkl[2048 * DIM];    // [Qw^T; Kw^T]
__device__ __half g_Wvh[DIM * DIM],   g_Wvl[DIM * DIM];      // Vw^T
__device__ __half g_QKh[NTOK * 2048], g_QKl[NTOK * 2048];    // Q | K splits
__device__ __half g_Vth[DIM * NTOK],  g_Vtl[DIM * NTOK];     // V^T [D, NTOK]
__device__ __half g_Ph[BATCH * SEQ * SEQ], g_Pl[BATCH * SEQ * SEQ];

// ---------------------------------------------------------------------------
// Helpers
// ---------------------------------------------------------------------------
__device__ __forceinline__ uint32_t smem_u32(const void* p) {
    uint32_t a;
    asm("{ .reg .u64 t; cvta.to.shared.u64 t, %1; cvt.u32.u64 %0, t; }" : "=r"(a) : "l"(p));
    return a;
}

#define CP16(dst, src) \
    asm volatile("cp.async.cg.shared.global [%0], [%1], 16;" :: "r"(dst), "l"(src))

#define LDSM4(r, addr) \
    asm volatile("ldmatrix.sync.aligned.m8n8.x4.shared.b16 {%0,%1,%2,%3}, [%4];" \
        : "=r"((r)[0]), "=r"((r)[1]), "=r"((r)[2]), "=r"((r)[3]) : "r"(addr))

// fp32-accumulate MMA (main product)
#define MMA4(c, a, b0, b1) \
    asm volatile("mma.sync.aligned.m16n8k16.row.col.f32.f16.f16.f32 " \
        "{%0,%1,%2,%3}, {%4,%5,%6,%7}, {%8,%9}, {%0,%1,%2,%3};" \
        : "+f"((c)[0]), "+f"((c)[1]), "+f"((c)[2]), "+f"((c)[3]) \
        : "r"((a)[0]), "r"((a)[1]), "r"((a)[2]), "r"((a)[3]), "r"(b0), "r"(b1))

// fp16-accumulate MMA (lo-correction products; values are ~2^-11 of main)
#define MMA2H(c, a, b0, b1) \
    asm volatile("mma.sync.aligned.m16n8k16.row.col.f16.f16.f16.f16 " \
        "{%0,%1}, {%2,%3,%4,%5}, {%6,%7}, {%0,%1};" \
        : "+r"((c)[0]), "+r"((c)[1]) \
        : "r"((a)[0]), "r"((a)[1]), "r"((a)[2]), "r"((a)[3]), "r"(b0), "r"(b1))

// ---------------------------------------------------------------------------
// HMMA GEMM: C[M,N] = A[M,K] @ B[N,K]^T, fp16 2-way split:
//   C = Ah*Bh (fp32 acc)  +  (Ah*Bl + Al*Bh) (fp16 acc, added at epilogue)
// CTA tile 128x128, BK=32, 8 warps (2x4), warp tile 64x32.
// 4-stage cp.async pipeline, one __syncthreads per K-step.
// MODE: 0 plain, 1 causal block-skip, 2 K clamped to brow0+128.
// EPI:  0 -> fp32 C;  1 -> fp16 hi/lo split (Ch, Cl).
// ---------------------------------------------------------------------------
#define TILE_B    10240            // 128 rows * 80B pitch
#define STAGE_B   (4 * TILE_B)     // Ah, Al, Bh, Bl
#define GEMM_SMEM (4 * STAGE_B)    // 4 stages = 163840 B

template <int MODE, int EPI>
__global__ void __launch_bounds__(256, 1)
gemm_hmma(const __half* __restrict__ Ah, const __half* __restrict__ Al,
          const __half* __restrict__ Bh, const __half* __restrict__ Bl,
          float* __restrict__ C, __half* __restrict__ Ch, __half* __restrict__ Cl,
          int K, int lda, int ldb, int ldc,
          long sA, long sB, long sC)
{
    const int brow0 = blockIdx.y * 128;
    const int bcol0 = blockIdx.x * 128;
    if (MODE == 1 && bcol0 > brow0) return;

    extern __shared__ char sm[];
    const uint32_t smb = smem_u32(sm);

    const int tid = threadIdx.x;
    const int lane = tid & 31;
    const int wid = tid >> 5;
    const int wr = wid >> 2;      // warp row: rows wr*64
    const int wc = wid & 3;       // warp col: cols wc*32

    Ah += (long)blockIdx.z * sA;  Al += (long)blockIdx.z * sA;
    Bh += (long)blockIdx.z * sB;  Bl += (long)blockIdx.z * sB;

    const int kend = (MODE == 2) ? (brow0 + 128) : K;
    const int nsteps = kend >> 5;

    // loader geometry: 256 threads x 16B, two row-halves per tile
    const int lrow = tid >> 2;
    const int lcol = tid & 3;
    const uint32_t so1 = (uint32_t)(lrow * 80 + lcol * 16);
    const uint32_t so2 = (uint32_t)((lrow + 64) * 80 + lcol * 16);

    auto load_stage = [&](int slot, int k0) {
        uint32_t st = smb + slot * STAGE_B;
        long gk = k0 + lcol * 8;
        CP16(st + 0 * TILE_B + so1, Ah + (long)(brow0 + lrow)      * lda + gk);
        CP16(st + 0 * TILE_B + so2, Ah + (long)(brow0 + lrow + 64) * lda + gk);
        CP16(st + 1 * TILE_B + so1, Al + (long)(brow0 + lrow)      * lda + gk);
        CP16(st + 1 * TILE_B + so2, Al + (long)(brow0 + lrow + 64) * lda + gk);
        CP16(st + 2 * TILE_B + so1, Bh + (long)(bcol0 + lrow)      * ldb + gk);
        CP16(st + 2 * TILE_B + so2, Bh + (long)(bcol0 + lrow + 64) * ldb + gk);
        CP16(st + 3 * TILE_B + so1, Bl + (long)(bcol0 + lrow)      * ldb + gk);
        CP16(st + 3 * TILE_B + so2, Bl + (long)(bcol0 + lrow + 64) * ldb + gk);
        asm volatile("cp.async.commit_group;");
    };

    float acc[4][4][4];
    uint32_t acc16[4][4][2];
#pragma unroll
    for (int mt = 0; mt < 4; mt++)
#pragma unroll
        for (int nt = 0; nt < 4; nt++) {
            acc16[mt][nt][0] = 0u; acc16[mt][nt][1] = 0u;
#pragma unroll
            for (int v = 0; v < 4; v++) acc[mt][nt][v] = 0.f;
        }

    const int arow = lane & 15;
    const int asel = lane >> 4;
    const int browi = (lane & 7) + ((lane >> 4) << 3);
    const int bsel = (lane >> 3) & 1;

    // prefetch 3 stages (always 3 commits to keep group counting uniform)
#pragma unroll
    for (int k = 0; k < 3; k++) {
        if (k < nsteps) load_stage(k, k * 32);
        else asm volatile("cp.async.commit_group;");
    }

    for (int s = 0; s < nsteps; s++) {
        asm volatile("cp.async.wait_group 2;");
        __syncthreads();

        const uint32_t st = smb + (s & 3) * STAGE_B;
#pragma unroll
        for (int kk = 0; kk < 2; kk++) {
            uint32_t aH[4][4], aL[4][4];
#pragma unroll
            for (int mt = 0; mt < 4; mt++) {
                uint32_t off = (uint32_t)((wr * 64 + mt * 16 + arow) * 80 + kk * 32 + asel * 16);
                LDSM4(aH[mt], st + 0 * TILE_B + off);
                LDSM4(aL[mt], st + 1 * TILE_B + off);
            }
            uint32_t bH[2][4], bL[2][4];
#pragma unroll
            for (int np = 0; np < 2; np++) {
                uint32_t off = (uint32_t)((wc * 32 + np * 16 + browi) * 80 + kk * 32 + bsel * 16);
                LDSM4(bH[np], st + 2 * TILE_B + off);
                LDSM4(bL[np], st + 3 * TILE_B + off);
            }
#pragma unroll
            for (int mt = 0; mt < 4; mt++)
#pragma unroll
                for (int nt = 0; nt < 4; nt++) {
                    const int np = nt >> 1, hv = (nt & 1) * 2;
                    MMA4(acc[mt][nt], aH[mt], bH[np][hv], bH[np][hv + 1]);
                    MMA2H(acc16[mt][nt], aH[mt], bL[np][hv], bL[np][hv + 1]);
                    MMA2H(acc16[mt][nt], aL[mt], bH[np][hv], bH[np][hv + 1]);
                }
        }

        if (s + 3 < nsteps) load_stage((s + 3) & 3, (s + 3) * 32);
        else asm volatile("cp.async.commit_group;");
    }

    // --- epilogue: combine fp32 main + fp16 lo-corrections ---
    const int erow = lane >> 2;
    const int ecol = (lane & 3) * 2;
#pragma unroll
    for (int mt = 0; mt < 4; mt++) {
        const int row = brow0 + wr * 64 + mt * 16 + erow;
#pragma unroll
        for (int nt = 0; nt < 4; nt++) {
            const int col = bcol0 + wc * 32 + nt * 8 + ecol;
            float2 lo0 = __half22float2(*(__half2*)&acc16[mt][nt][0]);
            float2 lo1 = __half22float2(*(__half2*)&acc16[mt][nt][1]);
            float c0 = acc[mt][nt][0] + lo0.x;
            float c1 = acc[mt][nt][1] + lo0.y;
            float c2 = acc[mt][nt][2] + lo1.x;
            float c3 = acc[mt][nt][3] + lo1.y;
            if (EPI == 0) {
                float* Cb = C + (long)blockIdx.z * sC;
                *(float2*)(Cb + (long)row * ldc + col)       = make_float2(c0, c1);
                *(float2*)(Cb + (long)(row + 8) * ldc + col) = make_float2(c2, c3);
            } else {
                __half* Hb = Ch + (long)blockIdx.z * sC;
                __half* Lb = Cl + (long)blockIdx.z * sC;
                __half h0 = __float2half_rn(c0), h1 = __float2half_rn(c1);
                __half h2 = __float2half_rn(c2), h3 = __float2half_rn(c3);
                *(__half2*)(Hb + (long)row * ldc + col)       = __halves2half2(h0, h1);
                *(__half2*)(Hb + (long)(row + 8) * ldc + col) = __halves2half2(h2, h3);
                *(__half2*)(Lb + (long)row * ldc + col) = __halves2half2(
                    __float2half_rn(c0 - __half2float(h0)), __float2half_rn(c1 - __half2float(h1)));
                *(__half2*)(Lb + (long)(row + 8) * ldc + col) = __halves2half2(
                    __float2half_rn(c2 - __half2float(h2)), __float2half_rn(c3 - __half2float(h3)));
            }
        }
    }
}

// ---------------------------------------------------------------------------
// Elementwise fp32 -> (hi, lo) fp16 split.
// ---------------------------------------------------------------------------
__global__ void __launch_bounds__(256)
split_fp32(const float* __restrict__ in, __half* __restrict__ hi,
           __half* __restrict__ lo, long n4)
{
    long i = (long)blockIdx.x * blockDim.x + threadIdx.x;
    long stride = (long)gridDim.x * blockDim.x;
    for (; i < n4; i += stride) {
        float4 v = ((const float4*)in)[i];
        float f[4] = {v.x, v.y, v.z, v.w};
        __half h[4], l[4];
#pragma unroll
        for (int j = 0; j < 4; j++) {
            h[j] = __float2half_rn(f[j]);
            l[j] = __float2half_rn(f[j] - __half2float(h[j]));
        }
        ((uint2*)hi)[i] = *(uint2*)h;
        ((uint2*)lo)[i] = *(uint2*)l;
    }
}

// ---------------------------------------------------------------------------
// Transpose + split: fp32 [R, C] -> fp16 hi/lo [C, R] (weights, 1024x1024).
// ---------------------------------------------------------------------------
__global__ void __launch_bounds__(256)
transpose_split(const float* __restrict__ in, __half* __restrict__ oh,
                __half* __restrict__ ol, int R, int Cc)
{
    __shared__ float tile[32][33];
    const int c0 = blockIdx.x * 32, r0 = blockIdx.y * 32;
#pragma unroll
    for (int dy = threadIdx.y; dy < 32; dy += 8)
        tile[dy][threadIdx.x] = in[(long)(r0 + dy) * Cc + c0 + threadIdx.x];
    __syncthreads();
#pragma unroll
    for (int dy = threadIdx.y; dy < 32; dy += 8) {
        float v = tile[threadIdx.x][dy];
        long o = (long)(c0 + dy) * R + r0 + threadIdx.x;
        __half h = __float2half_rn(v);
        oh[o] = h;
        ol[o] = __float2half_rn(v - __half2float(h));
    }
}

// ---------------------------------------------------------------------------
// Causal row softmax: fp32 scores -> fp16 hi/lo probs, zero-filled above diag.
// ---------------------------------------------------------------------------
__global__ void __launch_bounds__(256)
softmax_causal_split(const float* __restrict__ P, __half* __restrict__ Ph,
                     __half* __restrict__ Pl)
{
    const int q = blockIdx.x;
    const int b = blockIdx.y;
    const long rowoff = ((long)b * SEQ + q) * SEQ;
    const float* row = P + rowoff;
    __half* ph = Ph + rowoff;
    __half* pl = Pl + rowoff;
    const int n = q + 1;
    const float scale = 0.03125f;  // 1/sqrt(1024)

    const int tid = threadIdx.x;
    float vals[8];
    int cnt = 0;
    float m = -1e30f;
    for (int j = tid; j < n; j += 256) {
        float v = row[j] * scale;
        vals[cnt++] = v;
        m = fmaxf(m, v);
    }
    __shared__ float red[256];
    red[tid] = m;
    __syncthreads();
#pragma unroll
    for (int s = 128; s > 0; s >>= 1) {
        if (tid < s) red[tid] = fmaxf(red[tid], red[tid + s]);
        __syncthreads();
    }
    m = red[0];
    __syncthreads();
    float sum = 0.f;
    for (int i = 0; i < cnt; i++) { vals[i] = __expf(vals[i] - m); sum += vals[i]; }
    red[tid] = sum;
    __syncthreads();
#pragma unroll
    for (int s = 128; s > 0; s >>= 1) {
        if (tid < s) red[tid] += red[tid + s];
        __syncthreads();
    }
    const float inv = 1.0f / red[0];
    cnt = 0;
    for (int j = tid; j < n; j += 256) {
        float p = vals[cnt++] * inv;
        __half h = __float2half_rn(p);
        ph[j] = h;
        pl[j] = __float2half_rn(p - __half2float(h));
    }
    const __half z = __float2half_rn(0.f);
    for (int j = n + tid; j < SEQ; j += 256) { ph[j] = z; pl[j] = z; }
}

// ---------------------------------------------------------------------------
// Host launcher
// ---------------------------------------------------------------------------
extern "C" void kernel_launch(void* const* d_in, const int* in_sizes, int n_in,
                              void* d_out, int out_size)
{
    (void)in_sizes; (void)n_in; (void)out_size;
    const float* x  = (const float*)d_in[0];
    const float* Qw = (const float*)d_in[1];
    const float* Kw = (const float*)d_in[2];
    const float* Vw = (const float*)d_in[3];
    float* out = (float*)d_out;

    float *Pp;
    cudaGetSymbolAddress((void**)&Pp, g_P);
    __half *xh, *xl, *Wqkh, *Wqkl, *Wvh, *Wvl;
    __half *QKh, *QKl, *Vth, *Vtl, *Ph, *Pl;
    cudaGetSymbolAddress((void**)&xh,   g_xh);   cudaGetSymbolAddress((void**)&xl,   g_xl);
    cudaGetSymbolAddress((void**)&Wqkh, g_Wqkh); cudaGetSymbolAddress((void**)&Wqkl, g_Wqkl);
    cudaGetSymbolAddress((void**)&Wvh,  g_Wvh);  cudaGetSymbolAddress((void**)&Wvl,  g_Wvl);
    cudaGetSymbolAddress((void**)&QKh,  g_QKh);  cudaGetSymbolAddress((void**)&QKl,  g_QKl);
    cudaGetSymbolAddress((void**)&Vth,  g_Vth);  cudaGetSymbolAddress((void**)&Vtl,  g_Vtl);
    cudaGetSymbolAddress((void**)&Ph,   g_Ph);   cudaGetSymbolAddress((void**)&Pl,   g_Pl);

    cudaFuncSetAttribute(gemm_hmma<0,0>, cudaFuncAttributeMaxDynamicSharedMemorySize, GEMM_SMEM);
    cudaFuncSetAttribute(gemm_hmma<0,1>, cudaFuncAttributeMaxDynamicSharedMemorySize, GEMM_SMEM);
    cudaFuncSetAttribute(gemm_hmma<1,0>, cudaFuncAttributeMaxDynamicSharedMemorySize, GEMM_SMEM);
    cudaFuncSetAttribute(gemm_hmma<2,0>, cudaFuncAttributeMaxDynamicSharedMemorySize, GEMM_SMEM);

    // --- Split x; transpose+split weights (Qw^T,Kw^T concatenated; Vw^T) ---
    {
        split_fp32<<<1024, 256>>>(x, xh, xl, (long)NTOK * DIM / 4);
        dim3 tg(DIM / 32, DIM / 32, 1);
        dim3 tb(32, 8);
        transpose_split<<<tg, tb>>>(Qw, Wqkh,              Wqkl,              DIM, DIM);
        transpose_split<<<tg, tb>>>(Kw, Wqkh + DIM * DIM,  Wqkl + DIM * DIM,  DIM, DIM);
        transpose_split<<<tg, tb>>>(Vw, Wvh,               Wvl,               DIM, DIM);
    }

    // --- Fused Q+K projection: [NTOK,1024] @ [2048,1024]^T -> QK [NTOK,2048] ---
    {
        dim3 grid(2048 / 128, NTOK / 128, 1);
        gemm_hmma<0,1><<<grid, 256, GEMM_SMEM>>>(xh, xl, Wqkh, Wqkl,
                                                 nullptr, QKh, QKl,
                                                 DIM, DIM, DIM, 2048, 0, 0, 0);
    }

    // --- V^T projection: Vt[D,NTOK] = Vw^T[D,K] @ x[NTOK,K]^T ---
    {
        dim3 grid(NTOK / 128, DIM / 128, 1);
        gemm_hmma<0,1><<<grid, 256, GEMM_SMEM>>>(Wvh, Wvl, xh, xl,
                                                 nullptr, Vth, Vtl,
                                                 DIM, DIM, DIM, NTOK, 0, 0, 0);
    }

    // --- Scores = Q @ K^T per batch (causal block-skip), fp32 out ---
    {
        dim3 grid(SEQ / 128, SEQ / 128, BATCH);
        gemm_hmma<1,0><<<grid, 256, GEMM_SMEM>>>(QKh, QKl, QKh + 1024, QKl + 1024,
                                                 Pp, nullptr, nullptr,
                                                 DIM, 2048, 2048, SEQ,
                                                 (long)SEQ * 2048, (long)SEQ * 2048,
                                                 (long)SEQ * SEQ);
    }

    // --- Softmax: fp32 scores -> fp16 hi/lo probs ---
    softmax_causal_split<<<dim3(SEQ, BATCH, 1), 256>>>(Pp, Ph, Pl);

    // --- Out = P @ Vt^T per batch, K clamped causally ---
    {
        dim3 grid(DIM / 128, SEQ / 128, BATCH);
        gemm_hmma<2,0><<<grid, 256, GEMM_SMEM>>>(Ph, Pl, Vth, Vtl,
                                                 out, nullptr, nullptr,
                                                 SEQ, SEQ, NTOK, DIM,
                                                 (long)SEQ * SEQ, SEQ,
                                                 (long)SEQ * DIM);
    }
}

// round 5
// speedup vs baseline: 4.4348x; 1.4778x over previous
#include <cuda_runtime.h>
#include <cuda_fp16.h>
#include <math.h>
#include <stdint.h>

// Problem shape (fixed by reference): B=4, S=2048, D=1024
#define BATCH 4
#define SEQ   2048
#define DIM   1024
#define NTOK  (BATCH * SEQ)   // 8192

// ---------------------------------------------------------------------------
// Scratch (static device globals)
// ---------------------------------------------------------------------------
__device__ float g_P[BATCH * SEQ * SEQ];                     // fp32 scores

__device__ __half g_xh[NTOK * DIM],   g_xl[NTOK * DIM];
__device__ __half g_Wqkh[2048 * DIM], g_Wqkl[2048 * DIM];    // [Qw^T; Kw^T] hi/lo
__device__ __half g_Wvh[DIM * DIM],   g_Wvl[DIM * DIM];      // Vw^T (lo unused)
__device__ __half g_QKh[NTOK * 2048];                        // Q | K (hi only)
__device__ __half g_Vth[DIM * NTOK],  g_Vtl[DIM * NTOK];     // V^T [D, NTOK] hi/lo
__device__ __half g_Ph[BATCH * SEQ * SEQ];                   // probs (hi only)

// ---------------------------------------------------------------------------
// Helpers
// ---------------------------------------------------------------------------
__device__ __forceinline__ uint32_t smem_u32(const void* p) {
    uint32_t a;
    asm("{ .reg .u64 t; cvta.to.shared.u64 t, %1; cvt.u32.u64 %0, t; }" : "=r"(a) : "l"(p));
    return a;
}

#define CP16(dst, src) \
    asm volatile("cp.async.cg.shared.global [%0], [%1], 16;" :: "r"(dst), "l"(src))

#define LDSM4(r, addr) \
    asm volatile("ldmatrix.sync.aligned.m8n8.x4.shared.b16 {%0,%1,%2,%3}, [%4];" \
        : "=r"((r)[0]), "=r"((r)[1]), "=r"((r)[2]), "=r"((r)[3]) : "r"(addr))

// fp32-accumulate MMA (main product)
#define MMA4(c, a, b0, b1) \
    asm volatile("mma.sync.aligned.m16n8k16.row.col.f32.f16.f16.f32 " \
        "{%0,%1,%2,%3}, {%4,%5,%6,%7}, {%8,%9}, {%0,%1,%2,%3};" \
        : "+f"((c)[0]), "+f"((c)[1]), "+f"((c)[2]), "+f"((c)[3]) \
        : "r"((a)[0]), "r"((a)[1]), "r"((a)[2]), "r"((a)[3]), "r"(b0), "r"(b1))

// fp16-accumulate MMA (lo-correction products; values are ~2^-11 of main)
#define MMA2H(c, a, b0, b1) \
    asm volatile("mma.sync.aligned.m16n8k16.row.col.f16.f16.f16.f16 " \
        "{%0,%1}, {%2,%3,%4,%5}, {%6,%7}, {%0,%1};" \
        : "+r"((c)[0]), "+r"((c)[1]) \
        : "r"((a)[0]), "r"((a)[1]), "r"((a)[2]), "r"((a)[3]), "r"(b0), "r"(b1))

// ---------------------------------------------------------------------------
// HMMA GEMM: C[M,N] = A[M,K] @ B[N,K]^T, selectable split precision:
//   NP=1: Ah*Bh
//   NP=2: Ah*Bh + Ah*Bl          (fp16-acc correction)
//   NP=3: Ah*Bh + Ah*Bl + Al*Bh  (fp16-acc corrections)
// CTA tile 128x128, BK=32, 8 warps (2x4), warp tile 64x32.
// 4-stage cp.async pipeline.
// MODE: 0 plain, 1 causal block-skip, 2 K clamped to brow0+128.
// EPI:  0 -> fp32 C;  1 -> fp16 hi/lo split (Ch, Cl);  2 -> fp16 hi only.
// ---------------------------------------------------------------------------
#define TILE_B 10240               // 128 rows * 80B pitch

template <int MODE, int EPI, int NP>
__global__ void __launch_bounds__(256, 1)
gemm_hmma(const __half* __restrict__ Ah, const __half* __restrict__ Al,
          const __half* __restrict__ Bh, const __half* __restrict__ Bl,
          float* __restrict__ C, __half* __restrict__ Ch, __half* __restrict__ Cl,
          int K, int lda, int ldb, int ldc,
          long sA, long sB, long sC)
{
    constexpr int NT = NP + 1;             // tiles per stage
    constexpr uint32_t STAGE = NT * TILE_B;
    constexpr uint32_t OFF_AH = 0;
    constexpr uint32_t OFF_BH = TILE_B;
    constexpr uint32_t OFF_BL = 2 * TILE_B;   // valid when NP >= 2
    constexpr uint32_t OFF_AL = 3 * TILE_B;   // valid when NP == 3

    const int brow0 = blockIdx.y * 128;
    const int bcol0 = blockIdx.x * 128;
    if (MODE == 1 && bcol0 > brow0) return;

    extern __shared__ char sm[];
    const uint32_t smb = smem_u32(sm);

    const int tid = threadIdx.x;
    const int lane = tid & 31;
    const int wid = tid >> 5;
    const int wr = wid >> 2;
    const int wc = wid & 3;

    Ah += (long)blockIdx.z * sA;
    if (NP == 3) Al += (long)blockIdx.z * sA;
    Bh += (long)blockIdx.z * sB;
    if (NP >= 2) Bl += (long)blockIdx.z * sB;

    const int kend = (MODE == 2) ? (brow0 + 128) : K;
    const int nsteps = kend >> 5;

    const int lrow = tid >> 2;
    const int lcol = tid & 3;
    const uint32_t so1 = (uint32_t)(lrow * 80 + lcol * 16);
    const uint32_t so2 = (uint32_t)((lrow + 64) * 80 + lcol * 16);

    auto load_stage = [&](int slot, int k0) {
        uint32_t st = smb + slot * STAGE;
        long gk = k0 + lcol * 8;
        CP16(st + OFF_AH + so1, Ah + (long)(brow0 + lrow)      * lda + gk);
        CP16(st + OFF_AH + so2, Ah + (long)(brow0 + lrow + 64) * lda + gk);
        CP16(st + OFF_BH + so1, Bh + (long)(bcol0 + lrow)      * ldb + gk);
        CP16(st + OFF_BH + so2, Bh + (long)(bcol0 + lrow + 64) * ldb + gk);
        if (NP >= 2) {
            CP16(st + OFF_BL + so1, Bl + (long)(bcol0 + lrow)      * ldb + gk);
            CP16(st + OFF_BL + so2, Bl + (long)(bcol0 + lrow + 64) * ldb + gk);
        }
        if (NP == 3) {
            CP16(st + OFF_AL + so1, Al + (long)(brow0 + lrow)      * lda + gk);
            CP16(st + OFF_AL + so2, Al + (long)(brow0 + lrow + 64) * lda + gk);
        }
        asm volatile("cp.async.commit_group;");
    };

    float acc[4][4][4];
    uint32_t acc16[4][4][2];
#pragma unroll
    for (int mt = 0; mt < 4; mt++)
#pragma unroll
        for (int nt = 0; nt < 4; nt++) {
            acc16[mt][nt][0] = 0u; acc16[mt][nt][1] = 0u;
#pragma unroll
            for (int v = 0; v < 4; v++) acc[mt][nt][v] = 0.f;
        }

    const int arow = lane & 15;
    const int asel = lane >> 4;
    const int browi = (lane & 7) + ((lane >> 4) << 3);
    const int bsel = (lane >> 3) & 1;

#pragma unroll
    for (int k = 0; k < 3; k++) {
        if (k < nsteps) load_stage(k, k * 32);
        else asm volatile("cp.async.commit_group;");
    }

    for (int s = 0; s < nsteps; s++) {
        asm volatile("cp.async.wait_group 2;");
        __syncthreads();

        const uint32_t st = smb + (s & 3) * STAGE;
#pragma unroll
        for (int kk = 0; kk < 2; kk++) {
            uint32_t aH[4][4], aL[4][4];
#pragma unroll
            for (int mt = 0; mt < 4; mt++) {
                uint32_t off = (uint32_t)((wr * 64 + mt * 16 + arow) * 80 + kk * 32 + asel * 16);
                LDSM4(aH[mt], st + OFF_AH + off);
                if (NP == 3) LDSM4(aL[mt], st + OFF_AL + off);
            }
            uint32_t bH[2][4], bL[2][4];
#pragma unroll
            for (int np = 0; np < 2; np++) {
                uint32_t off = (uint32_t)((wc * 32 + np * 16 + browi) * 80 + kk * 32 + bsel * 16);
                LDSM4(bH[np], st + OFF_BH + off);
                if (NP >= 2) LDSM4(bL[np], st + OFF_BL + off);
            }
#pragma unroll
            for (int mt = 0; mt < 4; mt++)
#pragma unroll
                for (int nt = 0; nt < 4; nt++) {
                    const int np = nt >> 1, hv = (nt & 1) * 2;
                    MMA4(acc[mt][nt], aH[mt], bH[np][hv], bH[np][hv + 1]);
                    if (NP >= 2) MMA2H(acc16[mt][nt], aH[mt], bL[np][hv], bL[np][hv + 1]);
                    if (NP == 3) MMA2H(acc16[mt][nt], aL[mt], bH[np][hv], bH[np][hv + 1]);
                }
        }

        if (s + 3 < nsteps) load_stage((s + 3) & 3, (s + 3) * 32);
        else asm volatile("cp.async.commit_group;");
    }

    // --- epilogue ---
    const int erow = lane >> 2;
    const int ecol = (lane & 3) * 2;
#pragma unroll
    for (int mt = 0; mt < 4; mt++) {
        const int row = brow0 + wr * 64 + mt * 16 + erow;
#pragma unroll
        for (int nt = 0; nt < 4; nt++) {
            const int col = bcol0 + wc * 32 + nt * 8 + ecol;
            float c0 = acc[mt][nt][0], c1 = acc[mt][nt][1];
            float c2 = acc[mt][nt][2], c3 = acc[mt][nt][3];
            if (NP >= 2) {
                float2 lo0 = __half22float2(*(__half2*)&acc16[mt][nt][0]);
                float2 lo1 = __half22float2(*(__half2*)&acc16[mt][nt][1]);
                c0 += lo0.x; c1 += lo0.y; c2 += lo1.x; c3 += lo1.y;
            }
            if (EPI == 0) {
                float* Cb = C + (long)blockIdx.z * sC;
                *(float2*)(Cb + (long)row * ldc + col)       = make_float2(c0, c1);
                *(float2*)(Cb + (long)(row + 8) * ldc + col) = make_float2(c2, c3);
            } else {
                __half* Hb = Ch + (long)blockIdx.z * sC;
                __half h0 = __float2half_rn(c0), h1 = __float2half_rn(c1);
                __half h2 = __float2half_rn(c2), h3 = __float2half_rn(c3);
                *(__half2*)(Hb + (long)row * ldc + col)       = __halves2half2(h0, h1);
                *(__half2*)(Hb + (long)(row + 8) * ldc + col) = __halves2half2(h2, h3);
                if (EPI == 1) {
                    __half* Lb = Cl + (long)blockIdx.z * sC;
                    *(__half2*)(Lb + (long)row * ldc + col) = __halves2half2(
                        __float2half_rn(c0 - __half2float(h0)), __float2half_rn(c1 - __half2float(h1)));
                    *(__half2*)(Lb + (long)(row + 8) * ldc + col) = __halves2half2(
                        __float2half_rn(c2 - __half2float(h2)), __float2half_rn(c3 - __half2float(h3)));
                }
            }
        }
    }
}

// ---------------------------------------------------------------------------
// Elementwise fp32 -> (hi, lo) fp16 split.
// ---------------------------------------------------------------------------
__global__ void __launch_bounds__(256)
split_fp32(const float* __restrict__ in, __half* __restrict__ hi,
           __half* __restrict__ lo, long n4)
{
    long i = (long)blockIdx.x * blockDim.x + threadIdx.x;
    long stride = (long)gridDim.x * blockDim.x;
    for (; i < n4; i += stride) {
        float4 v = ((const float4*)in)[i];
        float f[4] = {v.x, v.y, v.z, v.w};
        __half h[4], l[4];
#pragma unroll
        for (int j = 0; j < 4; j++) {
            h[j] = __float2half_rn(f[j]);
            l[j] = __float2half_rn(f[j] - __half2float(h[j]));
        }
        ((uint2*)hi)[i] = *(uint2*)h;
        ((uint2*)lo)[i] = *(uint2*)l;
    }
}

// ---------------------------------------------------------------------------
// Transpose + split: fp32 [R, C] -> fp16 hi/lo [C, R] (weights, 1024x1024).
// ---------------------------------------------------------------------------
__global__ void __launch_bounds__(256)
transpose_split(const float* __restrict__ in, __half* __restrict__ oh,
                __half* __restrict__ ol, int R, int Cc)
{
    __shared__ float tile[32][33];
    const int c0 = blockIdx.x * 32, r0 = blockIdx.y * 32;
#pragma unroll
    for (int dy = threadIdx.y; dy < 32; dy += 8)
        tile[dy][threadIdx.x] = in[(long)(r0 + dy) * Cc + c0 + threadIdx.x];
    __syncthreads();
#pragma unroll
    for (int dy = threadIdx.y; dy < 32; dy += 8) {
        float v = tile[threadIdx.x][dy];
        long o = (long)(c0 + dy) * R + r0 + threadIdx.x;
        __half h = __float2half_rn(v);
        oh[o] = h;
        ol[o] = __float2half_rn(v - __half2float(h));
    }
}

// ---------------------------------------------------------------------------
// Causal row softmax: fp32 scores -> fp16 probs (hi only). Zero-fills only up
// to the 128-block boundary (PV never reads past it).
// ---------------------------------------------------------------------------
__global__ void __launch_bounds__(256)
softmax_causal(const float* __restrict__ P, __half* __restrict__ Ph)
{
    const int q = blockIdx.x;
    const int b = blockIdx.y;
    const long rowoff = ((long)b * SEQ + q) * SEQ;
    const float* row = P + rowoff;
    __half* ph = Ph + rowoff;
    const int n = q + 1;
    const int nblk = ((q >> 7) + 1) << 7;   // zero-fill limit
    const float scale = 0.03125f;  // 1/sqrt(1024)

    const int tid = threadIdx.x;
    float vals[8];
    int cnt = 0;
    float m = -1e30f;
    for (int j = tid; j < n; j += 256) {
        float v = row[j] * scale;
        vals[cnt++] = v;
        m = fmaxf(m, v);
    }
    __shared__ float red[256];
    red[tid] = m;
    __syncthreads();
#pragma unroll
    for (int s = 128; s > 0; s >>= 1) {
        if (tid < s) red[tid] = fmaxf(red[tid], red[tid + s]);
        __syncthreads();
    }
    m = red[0];
    __syncthreads();
    float sum = 0.f;
    for (int i = 0; i < cnt; i++) { vals[i] = __expf(vals[i] - m); sum += vals[i]; }
    red[tid] = sum;
    __syncthreads();
#pragma unroll
    for (int s = 128; s > 0; s >>= 1) {
        if (tid < s) red[tid] += red[tid + s];
        __syncthreads();
    }
    const float inv = 1.0f / red[0];
    cnt = 0;
    for (int j = tid; j < n; j += 256) ph[j] = __float2half_rn(vals[cnt++] * inv);
    const __half z = __float2half_rn(0.f);
    for (int j = n + tid; j < nblk; j += 256) ph[j] = z;
}

// ---------------------------------------------------------------------------
// Host launcher
// ---------------------------------------------------------------------------
extern "C" void kernel_launch(void* const* d_in, const int* in_sizes, int n_in,
                              void* d_out, int out_size)
{
    (void)in_sizes; (void)n_in; (void)out_size;
    const float* x  = (const float*)d_in[0];
    const float* Qw = (const float*)d_in[1];
    const float* Kw = (const float*)d_in[2];
    const float* Vw = (const float*)d_in[3];
    float* out = (float*)d_out;

    float* Pp;
    cudaGetSymbolAddress((void**)&Pp, g_P);
    __half *xh, *xl, *Wqkh, *Wqkl, *Wvh, *Wvl;
    __half *QKh, *Vth, *Vtl, *Ph;
    cudaGetSymbolAddress((void**)&xh,   g_xh);   cudaGetSymbolAddress((void**)&xl,   g_xl);
    cudaGetSymbolAddress((void**)&Wqkh, g_Wqkh); cudaGetSymbolAddress((void**)&Wqkl, g_Wqkl);
    cudaGetSymbolAddress((void**)&Wvh,  g_Wvh);  cudaGetSymbolAddress((void**)&Wvl,  g_Wvl);
    cudaGetSymbolAddress((void**)&QKh,  g_QKh);
    cudaGetSymbolAddress((void**)&Vth,  g_Vth);  cudaGetSymbolAddress((void**)&Vtl,  g_Vtl);
    cudaGetSymbolAddress((void**)&Ph,   g_Ph);

    const int SM_NP1 = 4 * 2 * TILE_B;   // 81920
    const int SM_NP2 = 4 * 3 * TILE_B;   // 122880
    cudaFuncSetAttribute(gemm_hmma<0,2,2>, cudaFuncAttributeMaxDynamicSharedMemorySize, SM_NP2);
    cudaFuncSetAttribute(gemm_hmma<0,1,2>, cudaFuncAttributeMaxDynamicSharedMemorySize, SM_NP2);
    cudaFuncSetAttribute(gemm_hmma<1,0,1>, cudaFuncAttributeMaxDynamicSharedMemorySize, SM_NP1);
    cudaFuncSetAttribute(gemm_hmma<2,0,2>, cudaFuncAttributeMaxDynamicSharedMemorySize, SM_NP2);

    // --- Split x; transpose+split weights ---
    {
        split_fp32<<<1024, 256>>>(x, xh, xl, (long)NTOK * DIM / 4);
        dim3 tg(DIM / 32, DIM / 32, 1);
        dim3 tb(32, 8);
        transpose_split<<<tg, tb>>>(Qw, Wqkh,             Wqkl,             DIM, DIM);
        transpose_split<<<tg, tb>>>(Kw, Wqkh + DIM * DIM, Wqkl + DIM * DIM, DIM, DIM);
        transpose_split<<<tg, tb>>>(Vw, Wvh,              Wvl,              DIM, DIM);
    }

    // --- Fused Q+K projection (2 products: xh*Wh + xh*Wl), hi-only output ---
    {
        dim3 grid(2048 / 128, NTOK / 128, 1);
        gemm_hmma<0,2,2><<<grid, 256, SM_NP2>>>(xh, nullptr, Wqkh, Wqkl,
                                                nullptr, QKh, nullptr,
                                                DIM, DIM, DIM, 2048, 0, 0, 0);
    }

    // --- V^T projection: Vt[D,NTOK] = Wvh @ (xh,xl)^T, hi/lo output ---
    {
        dim3 grid(NTOK / 128, DIM / 128, 1);
        gemm_hmma<0,1,2><<<grid, 256, SM_NP2>>>(Wvh, nullptr, xh, xl,
                                                nullptr, Vth, Vtl,
                                                DIM, DIM, DIM, NTOK, 0, 0, 0);
    }

    // --- Scores = Qh @ Kh^T per batch (causal block-skip, 1 product) ---
    {
        dim3 grid(SEQ / 128, SEQ / 128, BATCH);
        gemm_hmma<1,0,1><<<grid, 256, SM_NP1>>>(QKh, nullptr, QKh + 1024, nullptr,
                                                Pp, nullptr, nullptr,
                                                DIM, 2048, 2048, SEQ,
                                                (long)SEQ * 2048, (long)SEQ * 2048,
                                                (long)SEQ * SEQ);
    }

    // --- Softmax: fp32 scores -> fp16 probs (hi only) ---
    softmax_causal<<<dim3(SEQ, BATCH, 1), 256>>>(Pp, Ph);

    // --- Out = Ph @ (Vth,Vtl)^T per batch, K clamped causally (2 products) ---
    {
        dim3 grid(DIM / 128, SEQ / 128, BATCH);
        gemm_hmma<2,0,2><<<grid, 256, SM_NP2>>>(Ph, nullptr, Vth, Vtl,
                                                out, nullptr, nullptr,
                                                SEQ, SEQ, NTOK, DIM,
                                                (long)SEQ * SEQ, SEQ,
                                                (long)SEQ * DIM);
    }
}

// round 6
// speedup vs baseline: 5.9476x; 1.3411x over previous
#include <cuda_runtime.h>
#include <cuda_fp16.h>
#include <math.h>
#include <stdint.h>

// Problem shape (fixed by reference): B=4, S=2048, D=1024
#define BATCH 4
#define SEQ   2048
#define DIM   1024
#define NTOK  (BATCH * SEQ)   // 8192

// ---------------------------------------------------------------------------
// Scratch (static device globals)
// ---------------------------------------------------------------------------
__device__ __half g_xh[NTOK * DIM],   g_xl[NTOK * DIM];
__device__ __half g_Wqkh[2048 * DIM];                        // [Qw^T; Kw^T] hi
__device__ __half g_Wvh[DIM * DIM];                          // Vw^T hi
__device__ __half g_QKh[NTOK * 2048];                        // Q | K (hi only)
__device__ __half g_Vth[DIM * NTOK],  g_Vtl[DIM * NTOK];     // V^T [D, NTOK] hi/lo
__device__ __half g_Sh[BATCH * SEQ * SEQ];                   // raw fp16 scores
__device__ __half g_Ph[BATCH * SEQ * SEQ];                   // probs (hi only)

// ---------------------------------------------------------------------------
// Helpers
// ---------------------------------------------------------------------------
__device__ __forceinline__ uint32_t smem_u32(const void* p) {
    uint32_t a;
    asm("{ .reg .u64 t; cvta.to.shared.u64 t, %1; cvt.u32.u64 %0, t; }" : "=r"(a) : "l"(p));
    return a;
}

#define CP16(dst, src) \
    asm volatile("cp.async.cg.shared.global [%0], [%1], 16;" :: "r"(dst), "l"(src))

#define LDSM4(r, addr) \
    asm volatile("ldmatrix.sync.aligned.m8n8.x4.shared.b16 {%0,%1,%2,%3}, [%4];" \
        : "=r"((r)[0]), "=r"((r)[1]), "=r"((r)[2]), "=r"((r)[3]) : "r"(addr))

// fp32-accumulate MMA (main product)
#define MMA4(c, a, b0, b1) \
    asm volatile("mma.sync.aligned.m16n8k16.row.col.f32.f16.f16.f32 " \
        "{%0,%1,%2,%3}, {%4,%5,%6,%7}, {%8,%9}, {%0,%1,%2,%3};" \
        : "+f"((c)[0]), "+f"((c)[1]), "+f"((c)[2]), "+f"((c)[3]) \
        : "r"((a)[0]), "r"((a)[1]), "r"((a)[2]), "r"((a)[3]), "r"(b0), "r"(b1))

// fp16-accumulate MMA (lo-correction products; values are ~2^-11 of main)
#define MMA2H(c, a, b0, b1) \
    asm volatile("mma.sync.aligned.m16n8k16.row.col.f16.f16.f16.f16 " \
        "{%0,%1}, {%2,%3,%4,%5}, {%6,%7}, {%0,%1};" \
        : "+r"((c)[0]), "+r"((c)[1]) \
        : "r"((a)[0]), "r"((a)[1]), "r"((a)[2]), "r"((a)[3]), "r"(b0), "r"(b1))

// ---------------------------------------------------------------------------
// HMMA GEMM: C[M,N] = A[M,K] @ B[N,K]^T, selectable split precision:
//   NP=1: Ah*Bh
//   NP=2: Ah*Bh + Ah*Bl          (fp16-acc correction)
// CTA tile 128x128, BK=32, 8 warps (2x4), warp tile 64x32.
// 4-stage cp.async pipeline.
// MODE: 0 plain, 1 causal block-skip, 2 K clamped to brow0+128 with
//       heavy-rows-first scheduling (blockIdx.y reversed).
// EPI:  0 -> fp32 C;  1 -> fp16 hi/lo split (Ch, Cl);  2 -> fp16 hi only.
// ---------------------------------------------------------------------------
#define TILE_B 10240               // 128 rows * 80B pitch

template <int MODE, int EPI, int NP>
__global__ void __launch_bounds__(256, 1)
gemm_hmma(const __half* __restrict__ Ah,
          const __half* __restrict__ Bh, const __half* __restrict__ Bl,
          float* __restrict__ C, __half* __restrict__ Ch, __half* __restrict__ Cl,
          int K, int lda, int ldb, int ldc,
          long sA, long sB, long sC)
{
    constexpr int NT = NP + 1;             // tiles per stage
    constexpr uint32_t STAGE = NT * TILE_B;
    constexpr uint32_t OFF_AH = 0;
    constexpr uint32_t OFF_BH = TILE_B;
    constexpr uint32_t OFF_BL = 2 * TILE_B;   // valid when NP >= 2

    const int by = (MODE == 2) ? (gridDim.y - 1 - blockIdx.y) : blockIdx.y;
    const int brow0 = by * 128;
    const int bcol0 = blockIdx.x * 128;
    if (MODE == 1 && bcol0 > brow0) return;

    extern __shared__ char sm[];
    const uint32_t smb = smem_u32(sm);

    const int tid = threadIdx.x;
    const int lane = tid & 31;
    const int wid = tid >> 5;
    const int wr = wid >> 2;
    const int wc = wid & 3;

    Ah += (long)blockIdx.z * sA;
    Bh += (long)blockIdx.z * sB;
    if (NP >= 2) Bl += (long)blockIdx.z * sB;

    const int kend = (MODE == 2) ? (brow0 + 128) : K;
    const int nsteps = kend >> 5;

    const int lrow = tid >> 2;
    const int lcol = tid & 3;
    const uint32_t so1 = (uint32_t)(lrow * 80 + lcol * 16);
    const uint32_t so2 = (uint32_t)((lrow + 64) * 80 + lcol * 16);

    auto load_stage = [&](int slot, int k0) {
        uint32_t st = smb + slot * STAGE;
        long gk = k0 + lcol * 8;
        CP16(st + OFF_AH + so1, Ah + (long)(brow0 + lrow)      * lda + gk);
        CP16(st + OFF_AH + so2, Ah + (long)(brow0 + lrow + 64) * lda + gk);
        CP16(st + OFF_BH + so1, Bh + (long)(bcol0 + lrow)      * ldb + gk);
        CP16(st + OFF_BH + so2, Bh + (long)(bcol0 + lrow + 64) * ldb + gk);
        if (NP >= 2) {
            CP16(st + OFF_BL + so1, Bl + (long)(bcol0 + lrow)      * ldb + gk);
            CP16(st + OFF_BL + so2, Bl + (long)(bcol0 + lrow + 64) * ldb + gk);
        }
        asm volatile("cp.async.commit_group;");
    };

    float acc[4][4][4];
    uint32_t acc16[4][4][2];
#pragma unroll
    for (int mt = 0; mt < 4; mt++)
#pragma unroll
        for (int nt = 0; nt < 4; nt++) {
            acc16[mt][nt][0] = 0u; acc16[mt][nt][1] = 0u;
#pragma unroll
            for (int v = 0; v < 4; v++) acc[mt][nt][v] = 0.f;
        }

    const int arow = lane & 15;
    const int asel = lane >> 4;
    const int browi = (lane & 7) + ((lane >> 4) << 3);
    const int bsel = (lane >> 3) & 1;

#pragma unroll
    for (int k = 0; k < 3; k++) {
        if (k < nsteps) load_stage(k, k * 32);
        else asm volatile("cp.async.commit_group;");
    }

    for (int s = 0; s < nsteps; s++) {
        asm volatile("cp.async.wait_group 2;");
        __syncthreads();

        const uint32_t st = smb + (s & 3) * STAGE;
#pragma unroll
        for (int kk = 0; kk < 2; kk++) {
            uint32_t aH[4][4];
#pragma unroll
            for (int mt = 0; mt < 4; mt++) {
                uint32_t off = (uint32_t)((wr * 64 + mt * 16 + arow) * 80 + kk * 32 + asel * 16);
                LDSM4(aH[mt], st + OFF_AH + off);
            }
            uint32_t bH[2][4], bL[2][4];
#pragma unroll
            for (int np = 0; np < 2; np++) {
                uint32_t off = (uint32_t)((wc * 32 + np * 16 + browi) * 80 + kk * 32 + bsel * 16);
                LDSM4(bH[np], st + OFF_BH + off);
                if (NP >= 2) LDSM4(bL[np], st + OFF_BL + off);
            }
#pragma unroll
            for (int mt = 0; mt < 4; mt++)
#pragma unroll
                for (int nt = 0; nt < 4; nt++) {
                    const int np = nt >> 1, hv = (nt & 1) * 2;
                    MMA4(acc[mt][nt], aH[mt], bH[np][hv], bH[np][hv + 1]);
                    if (NP >= 2) MMA2H(acc16[mt][nt], aH[mt], bL[np][hv], bL[np][hv + 1]);
                }
        }

        if (s + 3 < nsteps) load_stage((s + 3) & 3, (s + 3) * 32);
        else asm volatile("cp.async.commit_group;");
    }

    // --- epilogue ---
    const int erow = lane >> 2;
    const int ecol = (lane & 3) * 2;
#pragma unroll
    for (int mt = 0; mt < 4; mt++) {
        const int row = brow0 + wr * 64 + mt * 16 + erow;
#pragma unroll
        for (int nt = 0; nt < 4; nt++) {
            const int col = bcol0 + wc * 32 + nt * 8 + ecol;
            float c0 = acc[mt][nt][0], c1 = acc[mt][nt][1];
            float c2 = acc[mt][nt][2], c3 = acc[mt][nt][3];
            if (NP >= 2) {
                float2 lo0 = __half22float2(*(__half2*)&acc16[mt][nt][0]);
                float2 lo1 = __half22float2(*(__half2*)&acc16[mt][nt][1]);
                c0 += lo0.x; c1 += lo0.y; c2 += lo1.x; c3 += lo1.y;
            }
            if (EPI == 0) {
                float* Cb = C + (long)blockIdx.z * sC;
                *(float2*)(Cb + (long)row * ldc + col)       = make_float2(c0, c1);
                *(float2*)(Cb + (long)(row + 8) * ldc + col) = make_float2(c2, c3);
            } else {
                __half* Hb = Ch + (long)blockIdx.z * sC;
                __half h0 = __float2half_rn(c0), h1 = __float2half_rn(c1);
                __half h2 = __float2half_rn(c2), h3 = __float2half_rn(c3);
                *(__half2*)(Hb + (long)row * ldc + col)       = __halves2half2(h0, h1);
                *(__half2*)(Hb + (long)(row + 8) * ldc + col) = __halves2half2(h2, h3);
                if (EPI == 1) {
                    __half* Lb = Cl + (long)blockIdx.z * sC;
                    *(__half2*)(Lb + (long)row * ldc + col) = __halves2half2(
                        __float2half_rn(c0 - __half2float(h0)), __float2half_rn(c1 - __half2float(h1)));
                    *(__half2*)(Lb + (long)(row + 8) * ldc + col) = __halves2half2(
                        __float2half_rn(c2 - __half2float(h2)), __float2half_rn(c3 - __half2float(h3)));
                }
            }
        }
    }
}

// ---------------------------------------------------------------------------
// Elementwise fp32 -> (hi, lo) fp16 split.
// ---------------------------------------------------------------------------
__global__ void __launch_bounds__(256)
split_fp32(const float* __restrict__ in, __half* __restrict__ hi,
           __half* __restrict__ lo, long n4)
{
    long i = (long)blockIdx.x * blockDim.x + threadIdx.x;
    long stride = (long)gridDim.x * blockDim.x;
    for (; i < n4; i += stride) {
        float4 v = ((const float4*)in)[i];
        float f[4] = {v.x, v.y, v.z, v.w};
        __half h[4], l[4];
#pragma unroll
        for (int j = 0; j < 4; j++) {
            h[j] = __float2half_rn(f[j]);
            l[j] = __float2half_rn(f[j] - __half2float(h[j]));
        }
        ((uint2*)hi)[i] = *(uint2*)h;
        ((uint2*)lo)[i] = *(uint2*)l;
    }
}

// ---------------------------------------------------------------------------
// Transpose (hi only): fp32 [R, C] -> fp16 [C, R] (weights, 1024x1024).
// ---------------------------------------------------------------------------
__global__ void __launch_bounds__(256)
transpose_hi(const float* __restrict__ in, __half* __restrict__ oh, int R, int Cc)
{
    __shared__ float tile[32][33];
    const int c0 = blockIdx.x * 32, r0 = blockIdx.y * 32;
#pragma unroll
    for (int dy = threadIdx.y; dy < 32; dy += 8)
        tile[dy][threadIdx.x] = in[(long)(r0 + dy) * Cc + c0 + threadIdx.x];
    __syncthreads();
#pragma unroll
    for (int dy = threadIdx.y; dy < 32; dy += 8) {
        float v = tile[threadIdx.x][dy];
        oh[(long)(c0 + dy) * R + r0 + threadIdx.x] = __float2half_rn(v);
    }
}

// ---------------------------------------------------------------------------
// Causal row softmax: fp16 raw scores -> fp16 probs. Applies 1/sqrt(D) scale.
// Zero-fills only to the 128-block boundary (PV never reads past it).
// ---------------------------------------------------------------------------
__global__ void __launch_bounds__(256)
softmax_causal(const __half* __restrict__ S, __half* __restrict__ Ph)
{
    const int q = blockIdx.x;
    const int b = blockIdx.y;
    const long rowoff = ((long)b * SEQ + q) * SEQ;
    const __half* row = S + rowoff;
    __half* ph = Ph + rowoff;
    const int n = q + 1;
    const int nblk = ((q >> 7) + 1) << 7;   // zero-fill limit
    const float scale = 0.03125f;  // 1/sqrt(1024)

    const int tid = threadIdx.x;
    float vals[8];
    int cnt = 0;
    float m = -1e30f;
    for (int j = tid; j < n; j += 256) {
        float v = __half2float(row[j]) * scale;
        vals[cnt++] = v;
        m = fmaxf(m, v);
    }
    __shared__ float red[256];
    red[tid] = m;
    __syncthreads();
#pragma unroll
    for (int s = 128; s > 0; s >>= 1) {
        if (tid < s) red[tid] = fmaxf(red[tid], red[tid + s]);
        __syncthreads();
    }
    m = red[0];
    __syncthreads();
    float sum = 0.f;
    for (int i = 0; i < cnt; i++) { vals[i] = __expf(vals[i] - m); sum += vals[i]; }
    red[tid] = sum;
    __syncthreads();
#pragma unroll
    for (int s = 128; s > 0; s >>= 1) {
        if (tid < s) red[tid] += red[tid + s];
        __syncthreads();
    }
    const float inv = 1.0f / red[0];
    cnt = 0;
    for (int j = tid; j < n; j += 256) ph[j] = __float2half_rn(vals[cnt++] * inv);
    const __half z = __float2half_rn(0.f);
    for (int j = n + tid; j < nblk; j += 256) ph[j] = z;
}

// ---------------------------------------------------------------------------
// Host launcher
// ---------------------------------------------------------------------------
extern "C" void kernel_launch(void* const* d_in, const int* in_sizes, int n_in,
                              void* d_out, int out_size)
{
    (void)in_sizes; (void)n_in; (void)out_size;
    const float* x  = (const float*)d_in[0];
    const float* Qw = (const float*)d_in[1];
    const float* Kw = (const float*)d_in[2];
    const float* Vw = (const float*)d_in[3];
    float* out = (float*)d_out;

    __half *xh, *xl, *Wqkh, *Wvh, *QKh, *Vth, *Vtl, *Sh, *Ph;
    cudaGetSymbolAddress((void**)&xh,   g_xh);   cudaGetSymbolAddress((void**)&xl,   g_xl);
    cudaGetSymbolAddress((void**)&Wqkh, g_Wqkh);
    cudaGetSymbolAddress((void**)&Wvh,  g_Wvh);
    cudaGetSymbolAddress((void**)&QKh,  g_QKh);
    cudaGetSymbolAddress((void**)&Vth,  g_Vth);  cudaGetSymbolAddress((void**)&Vtl,  g_Vtl);
    cudaGetSymbolAddress((void**)&Sh,   g_Sh);
    cudaGetSymbolAddress((void**)&Ph,   g_Ph);

    const int SM_NP1 = 4 * 2 * TILE_B;   // 81920
    const int SM_NP2 = 4 * 3 * TILE_B;   // 122880
    cudaFuncSetAttribute(gemm_hmma<0,2,1>, cudaFuncAttributeMaxDynamicSharedMemorySize, SM_NP1);
    cudaFuncSetAttribute(gemm_hmma<0,1,1>, cudaFuncAttributeMaxDynamicSharedMemorySize, SM_NP1);
    cudaFuncSetAttribute(gemm_hmma<1,2,1>, cudaFuncAttributeMaxDynamicSharedMemorySize, SM_NP1);
    cudaFuncSetAttribute(gemm_hmma<2,0,2>, cudaFuncAttributeMaxDynamicSharedMemorySize, SM_NP2);

    // --- Split x; transpose weights (hi only) ---
    {
        split_fp32<<<1024, 256>>>(x, xh, xl, (long)NTOK * DIM / 4);
        dim3 tg(DIM / 32, DIM / 32, 1);
        dim3 tb(32, 8);
        transpose_hi<<<tg, tb>>>(Qw, Wqkh,             DIM, DIM);
        transpose_hi<<<tg, tb>>>(Kw, Wqkh + DIM * DIM, DIM, DIM);
        transpose_hi<<<tg, tb>>>(Vw, Wvh,              DIM, DIM);
    }

    // --- Fused Q+K projection (1 product), hi-only output ---
    {
        dim3 grid(2048 / 128, NTOK / 128, 1);
        gemm_hmma<0,2,1><<<grid, 256, SM_NP1>>>(xh, Wqkh, nullptr,
                                                nullptr, QKh, nullptr,
                                                DIM, DIM, DIM, 2048, 0, 0, 0);
    }

    // --- V^T projection: Vt[D,NTOK] = Wvh @ xh^T (1 product), hi/lo output ---
    {
        dim3 grid(NTOK / 128, DIM / 128, 1);
        gemm_hmma<0,1,1><<<grid, 256, SM_NP1>>>(Wvh, xh, nullptr,
                                                nullptr, Vth, Vtl,
                                                DIM, DIM, DIM, NTOK, 0, 0, 0);
    }

    // --- Scores = Qh @ Kh^T per batch (causal block-skip), raw fp16 out ---
    {
        dim3 grid(SEQ / 128, SEQ / 128, BATCH);
        gemm_hmma<1,2,1><<<grid, 256, SM_NP1>>>(QKh, QKh + 1024, nullptr,
                                                nullptr, Sh, nullptr,
                                                DIM, 2048, 2048, SEQ,
                                                (long)SEQ * 2048, (long)SEQ * 2048,
                                                (long)SEQ * SEQ);
    }

    // --- Softmax: fp16 raw scores -> fp16 probs ---
    softmax_causal<<<dim3(SEQ, BATCH, 1), 256>>>(Sh, Ph);

    // --- Out = Ph @ (Vth,Vtl)^T per batch, K clamped, heavy rows first ---
    {
        dim3 grid(DIM / 128, SEQ / 128, BATCH);
        gemm_hmma<2,0,2><<<grid, 256, SM_NP2>>>(Ph, Vth, Vtl,
                                                out, nullptr, nullptr,
                                                SEQ, SEQ, NTOK, DIM,
                                                (long)SEQ * SEQ, SEQ,
                                                (long)SEQ * DIM);
    }
}

// round 7
// speedup vs baseline: 6.8137x; 1.1456x over previous
#include <cuda_runtime.h>
#include <cuda_fp16.h>
#include <math.h>
#include <stdint.h>

// Problem shape (fixed by reference): B=4, S=2048, D=1024
#define BATCH 4
#define SEQ   2048
#define DIM   1024
#define NTOK  (BATCH * SEQ)   // 8192

// ---------------------------------------------------------------------------
// Scratch (static device globals)
// ---------------------------------------------------------------------------
__device__ __half g_xh[NTOK * DIM];
__device__ __half g_Wqkh[2048 * DIM];                        // [Qw^T; Kw^T] hi
__device__ __half g_Wvh[DIM * DIM];                          // Vw^T hi
__device__ __half g_QKh[NTOK * 2048];                        // Q | K (hi only)
__device__ __half g_Vth[DIM * NTOK];                         // V^T [D, NTOK] hi
__device__ __half g_Sh[BATCH * SEQ * SEQ];                   // raw fp16 scores
__device__ __half g_Ph[BATCH * SEQ * SEQ];                   // probs

// ---------------------------------------------------------------------------
// Helpers
// ---------------------------------------------------------------------------
__device__ __forceinline__ uint32_t smem_u32(const void* p) {
    uint32_t a;
    asm("{ .reg .u64 t; cvta.to.shared.u64 t, %1; cvt.u32.u64 %0, t; }" : "=r"(a) : "l"(p));
    return a;
}

#define CP16(dst, src) \
    asm volatile("cp.async.cg.shared.global [%0], [%1], 16;" :: "r"(dst), "l"(src))

#define LDSM4(r, addr) \
    asm volatile("ldmatrix.sync.aligned.m8n8.x4.shared.b16 {%0,%1,%2,%3}, [%4];" \
        : "=r"((r)[0]), "=r"((r)[1]), "=r"((r)[2]), "=r"((r)[3]) : "r"(addr))

// fp32-accumulate MMA (main product)
#define MMA4(c, a, b0, b1) \
    asm volatile("mma.sync.aligned.m16n8k16.row.col.f32.f16.f16.f32 " \
        "{%0,%1,%2,%3}, {%4,%5,%6,%7}, {%8,%9}, {%0,%1,%2,%3};" \
        : "+f"((c)[0]), "+f"((c)[1]), "+f"((c)[2]), "+f"((c)[3]) \
        : "r"((a)[0]), "r"((a)[1]), "r"((a)[2]), "r"((a)[3]), "r"(b0), "r"(b1))

// fp16-accumulate MMA (lo-correction products)
#define MMA2H(c, a, b0, b1) \
    asm volatile("mma.sync.aligned.m16n8k16.row.col.f16.f16.f16.f16 " \
        "{%0,%1}, {%2,%3,%4,%5}, {%6,%7}, {%0,%1};" \
        : "+r"((c)[0]), "+r"((c)[1]) \
        : "r"((a)[0]), "r"((a)[1]), "r"((a)[2]), "r"((a)[3]), "r"(b0), "r"(b1))

// ---------------------------------------------------------------------------
// HMMA GEMM: C[M,N] = A[M,K] @ B[N,K]^T, selectable split precision:
//   NP=1: Ah*Bh
//   NP=2: Ah*Bh + Ah*Bl          (fp16-acc correction)
// CTA tile 128x128, BK=32, 8 warps (2x4), warp tile 64x32.
// 4-stage cp.async pipeline.
// MODE: 0 plain; 1 causal block-skip (heavy rows first); 2 K clamped to
//       brow0+128 (heavy rows first).
// EPI:  0 -> fp32 C;  1 -> fp16 hi/lo split (Ch, Cl);  2 -> fp16 hi only.
// ---------------------------------------------------------------------------
#define TILE_B 10240               // 128 rows * 80B pitch

template <int MODE, int EPI, int NP>
__global__ void __launch_bounds__(256, 1)
gemm_hmma(const __half* __restrict__ Ah,
          const __half* __restrict__ Bh, const __half* __restrict__ Bl,
          float* __restrict__ C, __half* __restrict__ Ch, __half* __restrict__ Cl,
          int K, int lda, int ldb, int ldc,
          long sA, long sB, long sC)
{
    constexpr int NT = NP + 1;             // tiles per stage
    constexpr uint32_t STAGE = NT * TILE_B;
    constexpr uint32_t OFF_AH = 0;
    constexpr uint32_t OFF_BH = TILE_B;
    constexpr uint32_t OFF_BL = 2 * TILE_B;   // valid when NP >= 2

    const int by = (MODE >= 1) ? (gridDim.y - 1 - blockIdx.y) : blockIdx.y;
    const int brow0 = by * 128;
    const int bcol0 = blockIdx.x * 128;
    if (MODE == 1 && bcol0 > brow0) return;

    extern __shared__ char sm[];
    const uint32_t smb = smem_u32(sm);

    const int tid = threadIdx.x;
    const int lane = tid & 31;
    const int wid = tid >> 5;
    const int wr = wid >> 2;
    const int wc = wid & 3;

    Ah += (long)blockIdx.z * sA;
    Bh += (long)blockIdx.z * sB;
    if (NP >= 2) Bl += (long)blockIdx.z * sB;

    const int kend = (MODE == 2) ? (brow0 + 128) : K;
    const int nsteps = kend >> 5;

    const int lrow = tid >> 2;
    const int lcol = tid & 3;
    const uint32_t so1 = (uint32_t)(lrow * 80 + lcol * 16);
    const uint32_t so2 = (uint32_t)((lrow + 64) * 80 + lcol * 16);

    auto load_stage = [&](int slot, int k0) {
        uint32_t st = smb + slot * STAGE;
        long gk = k0 + lcol * 8;
        CP16(st + OFF_AH + so1, Ah + (long)(brow0 + lrow)      * lda + gk);
        CP16(st + OFF_AH + so2, Ah + (long)(brow0 + lrow + 64) * lda + gk);
        CP16(st + OFF_BH + so1, Bh + (long)(bcol0 + lrow)      * ldb + gk);
        CP16(st + OFF_BH + so2, Bh + (long)(bcol0 + lrow + 64) * ldb + gk);
        if (NP >= 2) {
            CP16(st + OFF_BL + so1, Bl + (long)(bcol0 + lrow)      * ldb + gk);
            CP16(st + OFF_BL + so2, Bl + (long)(bcol0 + lrow + 64) * ldb + gk);
        }
        asm volatile("cp.async.commit_group;");
    };

    float acc[4][4][4];
    uint32_t acc16[4][4][2];
#pragma unroll
    for (int mt = 0; mt < 4; mt++)
#pragma unroll
        for (int nt = 0; nt < 4; nt++) {
            acc16[mt][nt][0] = 0u; acc16[mt][nt][1] = 0u;
#pragma unroll
            for (int v = 0; v < 4; v++) acc[mt][nt][v] = 0.f;
        }

    const int arow = lane & 15;
    const int asel = lane >> 4;
    const int browi = (lane & 7) + ((lane >> 4) << 3);
    const int bsel = (lane >> 3) & 1;

#pragma unroll
    for (int k = 0; k < 3; k++) {
        if (k < nsteps) load_stage(k, k * 32);
        else asm volatile("cp.async.commit_group;");
    }

    for (int s = 0; s < nsteps; s++) {
        asm volatile("cp.async.wait_group 2;");
        __syncthreads();

        const uint32_t st = smb + (s & 3) * STAGE;
#pragma unroll
        for (int kk = 0; kk < 2; kk++) {
            uint32_t aH[4][4];
#pragma unroll
            for (int mt = 0; mt < 4; mt++) {
                uint32_t off = (uint32_t)((wr * 64 + mt * 16 + arow) * 80 + kk * 32 + asel * 16);
                LDSM4(aH[mt], st + OFF_AH + off);
            }
            uint32_t bH[2][4], bL[2][4];
#pragma unroll
            for (int np = 0; np < 2; np++) {
                uint32_t off = (uint32_t)((wc * 32 + np * 16 + browi) * 80 + kk * 32 + bsel * 16);
                LDSM4(bH[np], st + OFF_BH + off);
                if (NP >= 2) LDSM4(bL[np], st + OFF_BL + off);
            }
#pragma unroll
            for (int mt = 0; mt < 4; mt++)
#pragma unroll
                for (int nt = 0; nt < 4; nt++) {
                    const int np = nt >> 1, hv = (nt & 1) * 2;
                    MMA4(acc[mt][nt], aH[mt], bH[np][hv], bH[np][hv + 1]);
                    if (NP >= 2) MMA2H(acc16[mt][nt], aH[mt], bL[np][hv], bL[np][hv + 1]);
                }
        }

        if (s + 3 < nsteps) load_stage((s + 3) & 3, (s + 3) * 32);
        else asm volatile("cp.async.commit_group;");
    }

    // --- epilogue ---
    const int erow = lane >> 2;
    const int ecol = (lane & 3) * 2;
#pragma unroll
    for (int mt = 0; mt < 4; mt++) {
        const int row = brow0 + wr * 64 + mt * 16 + erow;
#pragma unroll
        for (int nt = 0; nt < 4; nt++) {
            const int col = bcol0 + wc * 32 + nt * 8 + ecol;
            float c0 = acc[mt][nt][0], c1 = acc[mt][nt][1];
            float c2 = acc[mt][nt][2], c3 = acc[mt][nt][3];
            if (NP >= 2) {
                float2 lo0 = __half22float2(*(__half2*)&acc16[mt][nt][0]);
                float2 lo1 = __half22float2(*(__half2*)&acc16[mt][nt][1]);
                c0 += lo0.x; c1 += lo0.y; c2 += lo1.x; c3 += lo1.y;
            }
            if (EPI == 0) {
                float* Cb = C + (long)blockIdx.z * sC;
                *(float2*)(Cb + (long)row * ldc + col)       = make_float2(c0, c1);
                *(float2*)(Cb + (long)(row + 8) * ldc + col) = make_float2(c2, c3);
            } else {
                __half* Hb = Ch + (long)blockIdx.z * sC;
                __half h0 = __float2half_rn(c0), h1 = __float2half_rn(c1);
                __half h2 = __float2half_rn(c2), h3 = __float2half_rn(c3);
                *(__half2*)(Hb + (long)row * ldc + col)       = __halves2half2(h0, h1);
                *(__half2*)(Hb + (long)(row + 8) * ldc + col) = __halves2half2(h2, h3);
                if (EPI == 1) {
                    __half* Lb = Cl + (long)blockIdx.z * sC;
                    *(__half2*)(Lb + (long)row * ldc + col) = __halves2half2(
                        __float2half_rn(c0 - __half2float(h0)), __float2half_rn(c1 - __half2float(h1)));
                    *(__half2*)(Lb + (long)(row + 8) * ldc + col) = __halves2half2(
                        __float2half_rn(c2 - __half2float(h2)), __float2half_rn(c3 - __half2float(h3)));
                }
            }
        }
    }
}

// ---------------------------------------------------------------------------
// Elementwise fp32 -> fp16 (hi only).
// ---------------------------------------------------------------------------
__global__ void __launch_bounds__(256)
cvt_hi(const float* __restrict__ in, __half* __restrict__ hi, long n4)
{
    long i = (long)blockIdx.x * blockDim.x + threadIdx.x;
    long stride = (long)gridDim.x * blockDim.x;
    for (; i < n4; i += stride) {
        float4 v = ((const float4*)in)[i];
        __half h[4] = {__float2half_rn(v.x), __float2half_rn(v.y),
                       __float2half_rn(v.z), __float2half_rn(v.w)};
        ((uint2*)hi)[i] = *(uint2*)h;
    }
}

// ---------------------------------------------------------------------------
// Transpose (hi only): fp32 [R, C] -> fp16 [C, R] (weights, 1024x1024).
// ---------------------------------------------------------------------------
__global__ void __launch_bounds__(256)
transpose_hi(const float* __restrict__ in, __half* __restrict__ oh, int R, int Cc)
{
    __shared__ float tile[32][33];
    const int c0 = blockIdx.x * 32, r0 = blockIdx.y * 32;
#pragma unroll
    for (int dy = threadIdx.y; dy < 32; dy += 8)
        tile[dy][threadIdx.x] = in[(long)(r0 + dy) * Cc + c0 + threadIdx.x];
    __syncthreads();
#pragma unroll
    for (int dy = threadIdx.y; dy < 32; dy += 8) {
        float v = tile[threadIdx.x][dy];
        oh[(long)(c0 + dy) * R + r0 + threadIdx.x] = __float2half_rn(v);
    }
}

// ---------------------------------------------------------------------------
// Causal row softmax, vectorized: fp16 raw scores -> fp16 probs.
// Each thread owns one 8-half chunk (256 threads x 8 = 2048 = SEQ).
// Applies 1/sqrt(D); zero-fills to the 128-block boundary.
// ---------------------------------------------------------------------------
__global__ void __launch_bounds__(256)
softmax_causal(const __half* __restrict__ S, __half* __restrict__ Ph)
{
    const int q = blockIdx.x;
    const int b = blockIdx.y;
    const long rowoff = ((long)b * SEQ + q) * SEQ;
    const __half* row = S + rowoff;
    __half* ph = Ph + rowoff;
    const int n = q + 1;
    const int nblk = ((q >> 7) + 1) << 7;
    const float scale = 0.03125f;  // 1/sqrt(1024)

    const int tid = threadIdx.x;
    const int nch = n >> 3;           // full 8-elem chunks (<= 256)
    const int tail0 = nch << 3;
    const bool active = tid < nch;
    const bool hastail = (tail0 + tid) < n;   // tail len <= 7 -> tid < 8

    float vals[8];
    float m = -1e30f;
    if (active) {
        uint4 u = ((const uint4*)row)[tid];
        const __half2* hp = (const __half2*)&u;
#pragma unroll
        for (int i = 0; i < 4; i++) {
            float2 f = __half22float2(hp[i]);
            vals[2 * i]     = f.x * scale;
            vals[2 * i + 1] = f.y * scale;
            m = fmaxf(m, fmaxf(vals[2 * i], vals[2 * i + 1]));
        }
    }
    float tval = -1e30f;
    if (hastail) { tval = __half2float(row[tail0 + tid]) * scale; m = fmaxf(m, tval); }

    __shared__ float red[256];
    red[tid] = m;
    __syncthreads();
#pragma unroll
    for (int s = 128; s > 0; s >>= 1) {
        if (tid < s) red[tid] = fmaxf(red[tid], red[tid + s]);
        __syncthreads();
    }
    m = red[0];
    __syncthreads();

    float sum = 0.f;
    if (active) {
#pragma unroll
        for (int i = 0; i < 8; i++) { vals[i] = __expf(vals[i] - m); sum += vals[i]; }
    }
    float te = 0.f;
    if (hastail) { te = __expf(tval - m); sum += te; }

    red[tid] = sum;
    __syncthreads();
#pragma unroll
    for (int s = 128; s > 0; s >>= 1) {
        if (tid < s) red[tid] += red[tid + s];
        __syncthreads();
    }
    const float inv = 1.0f / red[0];

    if (active) {
        uint4 o;
        __half2* op = (__half2*)&o;
#pragma unroll
        for (int i = 0; i < 4; i++)
            op[i] = __halves2half2(__float2half_rn(vals[2 * i] * inv),
                                   __float2half_rn(vals[2 * i + 1] * inv));
        ((uint4*)ph)[tid] = o;
    }
    if (hastail) ph[tail0 + tid] = __float2half_rn(te * inv);
    const __half z = __float2half_rn(0.f);
    for (int j = n + tid; j < nblk; j += 256) ph[j] = z;
}

// ---------------------------------------------------------------------------
// Host launcher
// ---------------------------------------------------------------------------
extern "C" void kernel_launch(void* const* d_in, const int* in_sizes, int n_in,
                              void* d_out, int out_size)
{
    (void)in_sizes; (void)n_in; (void)out_size;
    const float* x  = (const float*)d_in[0];
    const float* Qw = (const float*)d_in[1];
    const float* Kw = (const float*)d_in[2];
    const float* Vw = (const float*)d_in[3];
    float* out = (float*)d_out;

    __half *xh, *Wqkh, *Wvh, *QKh, *Vth, *Sh, *Ph;
    cudaGetSymbolAddress((void**)&xh,   g_xh);
    cudaGetSymbolAddress((void**)&Wqkh, g_Wqkh);
    cudaGetSymbolAddress((void**)&Wvh,  g_Wvh);
    cudaGetSymbolAddress((void**)&QKh,  g_QKh);
    cudaGetSymbolAddress((void**)&Vth,  g_Vth);
    cudaGetSymbolAddress((void**)&Sh,   g_Sh);
    cudaGetSymbolAddress((void**)&Ph,   g_Ph);

    const int SM_NP1 = 4 * 2 * TILE_B;   // 81920
    cudaFuncSetAttribute(gemm_hmma<0,2,1>, cudaFuncAttributeMaxDynamicSharedMemorySize, SM_NP1);
    cudaFuncSetAttribute(gemm_hmma<1,2,1>, cudaFuncAttributeMaxDynamicSharedMemorySize, SM_NP1);
    cudaFuncSetAttribute(gemm_hmma<2,0,1>, cudaFuncAttributeMaxDynamicSharedMemorySize, SM_NP1);

    // --- Convert x; transpose weights (hi only) ---
    {
        cvt_hi<<<1024, 256>>>(x, xh, (long)NTOK * DIM / 4);
        dim3 tg(DIM / 32, DIM / 32, 1);
        dim3 tb(32, 8);
        transpose_hi<<<tg, tb>>>(Qw, Wqkh,             DIM, DIM);
        transpose_hi<<<tg, tb>>>(Kw, Wqkh + DIM * DIM, DIM, DIM);
        transpose_hi<<<tg, tb>>>(Vw, Wvh,              DIM, DIM);
    }

    // --- Fused Q+K projection (1 product), hi-only output ---
    {
        dim3 grid(2048 / 128, NTOK / 128, 1);
        gemm_hmma<0,2,1><<<grid, 256, SM_NP1>>>(xh, Wqkh, nullptr,
                                                nullptr, QKh, nullptr,
                                                DIM, DIM, DIM, 2048, 0, 0, 0);
    }

    // --- V^T projection: Vt[D,NTOK] = Wvh @ xh^T (1 product), hi only ---
    {
        dim3 grid(NTOK / 128, DIM / 128, 1);
        gemm_hmma<0,2,1><<<grid, 256, SM_NP1>>>(Wvh, xh, nullptr,
                                                nullptr, Vth, nullptr,
                                                DIM, DIM, DIM, NTOK, 0, 0, 0);
    }

    // --- Scores = Qh @ Kh^T per batch (causal skip, heavy rows first) ---
    {
        dim3 grid(SEQ / 128, SEQ / 128, BATCH);
        gemm_hmma<1,2,1><<<grid, 256, SM_NP1>>>(QKh, QKh + 1024, nullptr,
                                                nullptr, Sh, nullptr,
                                                DIM, 2048, 2048, SEQ,
                                                (long)SEQ * 2048, (long)SEQ * 2048,
                                                (long)SEQ * SEQ);
    }

    // --- Softmax: fp16 raw scores -> fp16 probs (vectorized) ---
    softmax_causal<<<dim3(SEQ, BATCH, 1), 256>>>(Sh, Ph);

    // --- Out = Ph @ Vth^T per batch, K clamped, heavy rows first (1 prod) ---
    {
        dim3 grid(DIM / 128, SEQ / 128, BATCH);
        gemm_hmma<2,0,1><<<grid, 256, SM_NP1>>>(Ph, Vth, nullptr,
                                                out, nullptr, nullptr,
                                                SEQ, SEQ, NTOK, DIM,
                                                (long)SEQ * SEQ, SEQ,
                                                (long)SEQ * DIM);
    }
}

// round 8
// speedup vs baseline: 7.2022x; 1.0570x over previous
#include <cuda_runtime.h>
#include <cuda_fp16.h>
#include <math.h>
#include <stdint.h>

// Problem shape (fixed by reference): B=4, S=2048, D=1024
#define BATCH 4
#define SEQ   2048
#define DIM   1024
#define NTOK  (BATCH * SEQ)   // 8192

// ---------------------------------------------------------------------------
// Scratch (static device globals)
// ---------------------------------------------------------------------------
__device__ __half g_xh[NTOK * DIM];
__device__ __half g_Wqkh[2048 * DIM];                        // [Qw^T; Kw^T] hi
__device__ __half g_Wvh[DIM * DIM];                          // Vw^T hi
__device__ __half g_QKh[NTOK * 2048];                        // Q | K (hi only)
__device__ __half g_Vth[DIM * NTOK];                         // V^T [D, NTOK] hi
__device__ __half g_Sh[BATCH * SEQ * SEQ];                   // raw fp16 scores
__device__ __half g_Ph[BATCH * SEQ * SEQ];                   // probs

// ---------------------------------------------------------------------------
// Helpers
// ---------------------------------------------------------------------------
__device__ __forceinline__ uint32_t smem_u32(const void* p) {
    uint32_t a;
    asm("{ .reg .u64 t; cvta.to.shared.u64 t, %1; cvt.u32.u64 %0, t; }" : "=r"(a) : "l"(p));
    return a;
}

#define CP16(dst, src) \
    asm volatile("cp.async.cg.shared.global [%0], [%1], 16;" :: "r"(dst), "l"(src))

#define LDSM4(r, addr) \
    asm volatile("ldmatrix.sync.aligned.m8n8.x4.shared.b16 {%0,%1,%2,%3}, [%4];" \
        : "=r"((r)[0]), "=r"((r)[1]), "=r"((r)[2]), "=r"((r)[3]) : "r"(addr))

// fp32-accumulate MMA
#define MMA4(c, a, b0, b1) \
    asm volatile("mma.sync.aligned.m16n8k16.row.col.f32.f16.f16.f32 " \
        "{%0,%1,%2,%3}, {%4,%5,%6,%7}, {%8,%9}, {%0,%1,%2,%3};" \
        : "+f"((c)[0]), "+f"((c)[1]), "+f"((c)[2]), "+f"((c)[3]) \
        : "r"((a)[0]), "r"((a)[1]), "r"((a)[2]), "r"((a)[3]), "r"(b0), "r"(b1))

// ---------------------------------------------------------------------------
// Projection GEMM: C[M,N] = A[M,K] @ B[N,K]^T, fp16 in / fp16 out (hi only).
// CTA tile 256x128, BK=32, 8 warps (4x2), warp tile 64x64.
// 4-stage cp.async pipeline. Plain (MODE 0) only.
// ---------------------------------------------------------------------------
#define TILE_AB 20480              // 256 rows * 80B pitch  (A tile)
#define TILE_BB 10240              // 128 rows * 80B pitch  (B tile)
#define STAGE_P (TILE_AB + TILE_BB)
#define SMEM_PROJ (4 * STAGE_P)    // 122880

__global__ void __launch_bounds__(256, 1)
gemm_proj(const __half* __restrict__ Ah, const __half* __restrict__ Bh,
          __half* __restrict__ Ch, int K, int lda, int ldb, int ldc)
{
    const int brow0 = blockIdx.y * 256;
    const int bcol0 = blockIdx.x * 128;

    extern __shared__ char sm[];
    const uint32_t smb = smem_u32(sm);

    const int tid = threadIdx.x;
    const int lane = tid & 31;
    const int wid = tid >> 5;
    const int wr = wid >> 1;      // 0..3 -> rows wr*64
    const int wc = wid & 1;       // 0..1 -> cols wc*64

    const int nsteps = K >> 5;

    const int lrow = tid >> 2;    // 0..63
    const int lcol = tid & 3;
    const uint32_t soA0 = (uint32_t)(lrow * 80 + lcol * 16);
    const uint32_t soB0 = soA0;

    auto load_stage = [&](int slot, int k0) {
        uint32_t st = smb + slot * STAGE_P;
        long gk = k0 + lcol * 8;
#pragma unroll
        for (int h = 0; h < 4; h++)
            CP16(st + soA0 + h * (64 * 80),
                 Ah + (long)(brow0 + lrow + h * 64) * lda + gk);
        CP16(st + TILE_AB + soB0,            Bh + (long)(bcol0 + lrow)      * ldb + gk);
        CP16(st + TILE_AB + soB0 + 64 * 80,  Bh + (long)(bcol0 + lrow + 64) * ldb + gk);
        asm volatile("cp.async.commit_group;");
    };

    float acc[4][8][4];
#pragma unroll
    for (int mt = 0; mt < 4; mt++)
#pragma unroll
        for (int nt = 0; nt < 8; nt++)
#pragma unroll
            for (int v = 0; v < 4; v++) acc[mt][nt][v] = 0.f;

    const int arow = lane & 15;
    const int asel = lane >> 4;
    const int browi = (lane & 7) + ((lane >> 4) << 3);
    const int bsel = (lane >> 3) & 1;

#pragma unroll
    for (int k = 0; k < 3; k++) {
        if (k < nsteps) load_stage(k, k * 32);
        else asm volatile("cp.async.commit_group;");
    }

    for (int s = 0; s < nsteps; s++) {
        asm volatile("cp.async.wait_group 2;");
        __syncthreads();

        const uint32_t st = smb + (s & 3) * STAGE_P;
#pragma unroll
        for (int kk = 0; kk < 2; kk++) {
            uint32_t aH[4][4];
#pragma unroll
            for (int mt = 0; mt < 4; mt++) {
                uint32_t off = (uint32_t)((wr * 64 + mt * 16 + arow) * 80 + kk * 32 + asel * 16);
                LDSM4(aH[mt], st + off);
            }
            uint32_t bH[4][4];
#pragma unroll
            for (int np = 0; np < 4; np++) {
                uint32_t off = (uint32_t)((wc * 64 + np * 16 + browi) * 80 + kk * 32 + bsel * 16);
                LDSM4(bH[np], st + TILE_AB + off);
            }
#pragma unroll
            for (int mt = 0; mt < 4; mt++)
#pragma unroll
                for (int nt = 0; nt < 8; nt++) {
                    const int np = nt >> 1, hv = (nt & 1) * 2;
                    MMA4(acc[mt][nt], aH[mt], bH[np][hv], bH[np][hv + 1]);
                }
        }

        if (s + 3 < nsteps) load_stage((s + 3) & 3, (s + 3) * 32);
        else asm volatile("cp.async.commit_group;");
    }

    // epilogue: fp16 hi only
    const int erow = lane >> 2;
    const int ecol = (lane & 3) * 2;
#pragma unroll
    for (int mt = 0; mt < 4; mt++) {
        const int row = brow0 + wr * 64 + mt * 16 + erow;
#pragma unroll
        for (int nt = 0; nt < 8; nt++) {
            const int col = bcol0 + wc * 64 + nt * 8 + ecol;
            const float* c = acc[mt][nt];
            *(__half2*)(Ch + (long)row * ldc + col) =
                __halves2half2(__float2half_rn(c[0]), __float2half_rn(c[1]));
            *(__half2*)(Ch + (long)(row + 8) * ldc + col) =
                __halves2half2(__float2half_rn(c[2]), __float2half_rn(c[3]));
        }
    }
}

// ---------------------------------------------------------------------------
// Attention GEMM (scores / PV): C[M,N] = A[M,K] @ B[N,K]^T, fp16 single
// product. CTA tile 128x128, BK=32, 8 warps (2x4), warp tile 64x32.
// MODE: 1 causal block-skip (heavy rows first); 2 K clamped to brow0+128
//       (heavy rows first).
// EPI:  0 -> fp32 C;  2 -> fp16 hi only.
// ---------------------------------------------------------------------------
#define TILE_B 10240               // 128 rows * 80B pitch
#define SMEM_ATT (4 * 2 * TILE_B)  // 81920

template <int MODE, int EPI>
__global__ void __launch_bounds__(256, 1)
gemm_att(const __half* __restrict__ Ah, const __half* __restrict__ Bh,
         float* __restrict__ C, __half* __restrict__ Ch,
         int K, int lda, int ldb, int ldc,
         long sA, long sB, long sC)
{
    const int by = gridDim.y - 1 - blockIdx.y;   // heavy rows first
    const int brow0 = by * 128;
    const int bcol0 = blockIdx.x * 128;
    if (MODE == 1 && bcol0 > brow0) return;

    extern __shared__ char sm[];
    const uint32_t smb = smem_u32(sm);

    const int tid = threadIdx.x;
    const int lane = tid & 31;
    const int wid = tid >> 5;
    const int wr = wid >> 2;
    const int wc = wid & 3;

    Ah += (long)blockIdx.z * sA;
    Bh += (long)blockIdx.z * sB;

    const int kend = (MODE == 2) ? (brow0 + 128) : K;
    const int nsteps = kend >> 5;

    const int lrow = tid >> 2;
    const int lcol = tid & 3;
    const uint32_t so1 = (uint32_t)(lrow * 80 + lcol * 16);
    const uint32_t so2 = (uint32_t)((lrow + 64) * 80 + lcol * 16);

    auto load_stage = [&](int slot, int k0) {
        uint32_t st = smb + slot * (2 * TILE_B);
        long gk = k0 + lcol * 8;
        CP16(st + so1,          Ah + (long)(brow0 + lrow)      * lda + gk);
        CP16(st + so2,          Ah + (long)(brow0 + lrow + 64) * lda + gk);
        CP16(st + TILE_B + so1, Bh + (long)(bcol0 + lrow)      * ldb + gk);
        CP16(st + TILE_B + so2, Bh + (long)(bcol0 + lrow + 64) * ldb + gk);
        asm volatile("cp.async.commit_group;");
    };

    float acc[4][4][4];
#pragma unroll
    for (int mt = 0; mt < 4; mt++)
#pragma unroll
        for (int nt = 0; nt < 4; nt++)
#pragma unroll
            for (int v = 0; v < 4; v++) acc[mt][nt][v] = 0.f;

    const int arow = lane & 15;
    const int asel = lane >> 4;
    const int browi = (lane & 7) + ((lane >> 4) << 3);
    const int bsel = (lane >> 3) & 1;

#pragma unroll
    for (int k = 0; k < 3; k++) {
        if (k < nsteps) load_stage(k, k * 32);
        else asm volatile("cp.async.commit_group;");
    }

    for (int s = 0; s < nsteps; s++) {
        asm volatile("cp.async.wait_group 2;");
        __syncthreads();

        const uint32_t st = smb + (s & 3) * (2 * TILE_B);
#pragma unroll
        for (int kk = 0; kk < 2; kk++) {
            uint32_t aH[4][4];
#pragma unroll
            for (int mt = 0; mt < 4; mt++) {
                uint32_t off = (uint32_t)((wr * 64 + mt * 16 + arow) * 80 + kk * 32 + asel * 16);
                LDSM4(aH[mt], st + off);
            }
            uint32_t bH[2][4];
#pragma unroll
            for (int np = 0; np < 2; np++) {
                uint32_t off = (uint32_t)((wc * 32 + np * 16 + browi) * 80 + kk * 32 + bsel * 16);
                LDSM4(bH[np], st + TILE_B + off);
            }
#pragma unroll
            for (int mt = 0; mt < 4; mt++)
#pragma unroll
                for (int nt = 0; nt < 4; nt++) {
                    const int np = nt >> 1, hv = (nt & 1) * 2;
                    MMA4(acc[mt][nt], aH[mt], bH[np][hv], bH[np][hv + 1]);
                }
        }

        if (s + 3 < nsteps) load_stage((s + 3) & 3, (s + 3) * 32);
        else asm volatile("cp.async.commit_group;");
    }

    const int erow = lane >> 2;
    const int ecol = (lane & 3) * 2;
#pragma unroll
    for (int mt = 0; mt < 4; mt++) {
        const int row = brow0 + wr * 64 + mt * 16 + erow;
#pragma unroll
        for (int nt = 0; nt < 4; nt++) {
            const int col = bcol0 + wc * 32 + nt * 8 + ecol;
            const float* c = acc[mt][nt];
            if (EPI == 0) {
                float* Cb = C + (long)blockIdx.z * sC;
                *(float2*)(Cb + (long)row * ldc + col)       = make_float2(c[0], c[1]);
                *(float2*)(Cb + (long)(row + 8) * ldc + col) = make_float2(c[2], c[3]);
            } else {
                __half* Hb = Ch + (long)blockIdx.z * sC;
                *(__half2*)(Hb + (long)row * ldc + col) =
                    __halves2half2(__float2half_rn(c[0]), __float2half_rn(c[1]));
                *(__half2*)(Hb + (long)(row + 8) * ldc + col) =
                    __halves2half2(__float2half_rn(c[2]), __float2half_rn(c[3]));
            }
        }
    }
}

// ---------------------------------------------------------------------------
// Elementwise fp32 -> fp16 (hi only).
// ---------------------------------------------------------------------------
__global__ void __launch_bounds__(256)
cvt_hi(const float* __restrict__ in, __half* __restrict__ hi, long n4)
{
    long i = (long)blockIdx.x * blockDim.x + threadIdx.x;
    long stride = (long)gridDim.x * blockDim.x;
    for (; i < n4; i += stride) {
        float4 v = ((const float4*)in)[i];
        __half h[4] = {__float2half_rn(v.x), __float2half_rn(v.y),
                       __float2half_rn(v.z), __float2half_rn(v.w)};
        ((uint2*)hi)[i] = *(uint2*)h;
    }
}

// ---------------------------------------------------------------------------
// Batched weight transpose: z=0 Qw -> Wqkh[0:], z=1 Kw -> Wqkh[DIM*DIM:],
// z=2 Vw -> Wvh. fp32 [1024,1024] -> fp16 transposed.
// ---------------------------------------------------------------------------
__global__ void __launch_bounds__(256)
transpose_w(const float* __restrict__ Qw, const float* __restrict__ Kw,
            const float* __restrict__ Vw, __half* __restrict__ Wqkh,
            __half* __restrict__ Wvh)
{
    __shared__ float tile[32][33];
    const int z = blockIdx.z;
    const float* src = (z == 0) ? Qw : (z == 1) ? Kw : Vw;
    __half* dst = (z == 0) ? Wqkh : (z == 1) ? (Wqkh + DIM * DIM) : Wvh;

    const int c0 = blockIdx.x * 32, r0 = blockIdx.y * 32;
#pragma unroll
    for (int dy = threadIdx.y; dy < 32; dy += 8)
        tile[dy][threadIdx.x] = src[(long)(r0 + dy) * DIM + c0 + threadIdx.x];
    __syncthreads();
#pragma unroll
    for (int dy = threadIdx.y; dy < 32; dy += 8) {
        float v = tile[threadIdx.x][dy];
        dst[(long)(c0 + dy) * DIM + r0 + threadIdx.x] = __float2half_rn(v);
    }
}

// ---------------------------------------------------------------------------
// Causal row softmax, vectorized: fp16 raw scores -> fp16 probs.
// ---------------------------------------------------------------------------
__global__ void __launch_bounds__(256)
softmax_causal(const __half* __restrict__ S, __half* __restrict__ Ph)
{
    const int q = blockIdx.x;
    const int b = blockIdx.y;
    const long rowoff = ((long)b * SEQ + q) * SEQ;
    const __half* row = S + rowoff;
    __half* ph = Ph + rowoff;
    const int n = q + 1;
    const int nblk = ((q >> 7) + 1) << 7;
    const float scale = 0.03125f;  // 1/sqrt(1024)

    const int tid = threadIdx.x;
    const int nch = n >> 3;
    const int tail0 = nch << 3;
    const bool active = tid < nch;
    const bool hastail = (tail0 + tid) < n;

    float vals[8];
    float m = -1e30f;
    if (active) {
        uint4 u = ((const uint4*)row)[tid];
        const __half2* hp = (const __half2*)&u;
#pragma unroll
        for (int i = 0; i < 4; i++) {
            float2 f = __half22float2(hp[i]);
            vals[2 * i]     = f.x * scale;
            vals[2 * i + 1] = f.y * scale;
            m = fmaxf(m, fmaxf(vals[2 * i], vals[2 * i + 1]));
        }
    }
    float tval = -1e30f;
    if (hastail) { tval = __half2float(row[tail0 + tid]) * scale; m = fmaxf(m, tval); }

    __shared__ float red[256];
    red[tid] = m;
    __syncthreads();
#pragma unroll
    for (int s = 128; s > 0; s >>= 1) {
        if (tid < s) red[tid] = fmaxf(red[tid], red[tid + s]);
        __syncthreads();
    }
    m = red[0];
    __syncthreads();

    float sum = 0.f;
    if (active) {
#pragma unroll
        for (int i = 0; i < 8; i++) { vals[i] = __expf(vals[i] - m); sum += vals[i]; }
    }
    float te = 0.f;
    if (hastail) { te = __expf(tval - m); sum += te; }

    red[tid] = sum;
    __syncthreads();
#pragma unroll
    for (int s = 128; s > 0; s >>= 1) {
        if (tid < s) red[tid] += red[tid + s];
        __syncthreads();
    }
    const float inv = 1.0f / red[0];

    if (active) {
        uint4 o;
        __half2* op = (__half2*)&o;
#pragma unroll
        for (int i = 0; i < 4; i++)
            op[i] = __halves2half2(__float2half_rn(vals[2 * i] * inv),
                                   __float2half_rn(vals[2 * i + 1] * inv));
        ((uint4*)ph)[tid] = o;
    }
    if (hastail) ph[tail0 + tid] = __float2half_rn(te * inv);
    const __half z = __float2half_rn(0.f);
    for (int j = n + tid; j < nblk; j += 256) ph[j] = z;
}

// ---------------------------------------------------------------------------
// Host launcher
// ---------------------------------------------------------------------------
extern "C" void kernel_launch(void* const* d_in, const int* in_sizes, int n_in,
                              void* d_out, int out_size)
{
    (void)in_sizes; (void)n_in; (void)out_size;
    const float* x  = (const float*)d_in[0];
    const float* Qw = (const float*)d_in[1];
    const float* Kw = (const float*)d_in[2];
    const float* Vw = (const float*)d_in[3];
    float* out = (float*)d_out;

    __half *xh, *Wqkh, *Wvh, *QKh, *Vth, *Sh, *Ph;
    cudaGetSymbolAddress((void**)&xh,   g_xh);
    cudaGetSymbolAddress((void**)&Wqkh, g_Wqkh);
    cudaGetSymbolAddress((void**)&Wvh,  g_Wvh);
    cudaGetSymbolAddress((void**)&QKh,  g_QKh);
    cudaGetSymbolAddress((void**)&Vth,  g_Vth);
    cudaGetSymbolAddress((void**)&Sh,   g_Sh);
    cudaGetSymbolAddress((void**)&Ph,   g_Ph);

    cudaFuncSetAttribute(gemm_proj,     cudaFuncAttributeMaxDynamicSharedMemorySize, SMEM_PROJ);
    cudaFuncSetAttribute(gemm_att<1,2>, cudaFuncAttributeMaxDynamicSharedMemorySize, SMEM_ATT);
    cudaFuncSetAttribute(gemm_att<2,0>, cudaFuncAttributeMaxDynamicSharedMemorySize, SMEM_ATT);

    // --- Convert x; transpose weights (one batched launch) ---
    {
        cvt_hi<<<1024, 256>>>(x, xh, (long)NTOK * DIM / 4);
        dim3 tg(DIM / 32, DIM / 32, 3);
        dim3 tb(32, 8);
        transpose_w<<<tg, tb>>>(Qw, Kw, Vw, Wqkh, Wvh);
    }

    // --- Fused Q+K projection: [NTOK,1024] @ [2048,1024]^T ---
    {
        dim3 grid(2048 / 128, NTOK / 256, 1);
        gemm_proj<<<grid, 256, SMEM_PROJ>>>(xh, Wqkh, QKh, DIM, DIM, DIM, 2048);
    }

    // --- V^T projection: Vt[D,NTOK] = Wvh @ xh^T ---
    {
        dim3 grid(NTOK / 128, DIM / 256, 1);
        gemm_proj<<<grid, 256, SMEM_PROJ>>>(Wvh, xh, Vth, DIM, DIM, DIM, NTOK);
    }

    // --- Scores = Qh @ Kh^T per batch (causal skip, heavy rows first) ---
    {
        dim3 grid(SEQ / 128, SEQ / 128, BATCH);
        gemm_att<1,2><<<grid, 256, SMEM_ATT>>>(QKh, QKh + 1024,
                                               nullptr, Sh,
                                               DIM, 2048, 2048, SEQ,
                                               (long)SEQ * 2048, (long)SEQ * 2048,
                                               (long)SEQ * SEQ);
    }

    // --- Softmax: fp16 raw scores -> fp16 probs (vectorized) ---
    softmax_causal<<<dim3(SEQ, BATCH, 1), 256>>>(Sh, Ph);

    // --- Out = Ph @ Vth^T per batch, K clamped, heavy rows first ---
    {
        dim3 grid(DIM / 128, SEQ / 128, BATCH);
        gemm_att<2,0><<<grid, 256, SMEM_ATT>>>(Ph, Vth,
                                               out, nullptr,
                                               SEQ, SEQ, NTOK, DIM,
                                               (long)SEQ * SEQ, SEQ,
                                               (long)SEQ * DIM);
    }
}